// round 10
// baseline (speedup 1.0000x reference)
#include <cuda_runtime.h>
#include <cuda_bf16.h>
#include <cstdint>

#define SIXH 6144
#define TT 256
#define MB 64
#define HH 1024
#define DD 512

// ---------------- scratch (device globals; no runtime allocation) ----------
__device__ float g_xz[(size_t)TT * MB * SIXH];   // 402 MB: xz then z per step
__device__ float g_h0all[(size_t)TT * MB * HH];  // 67 MB: layer-0 all_h
__device__ float g_whhi[(size_t)HH * SIXH];      // 25 MB: Wh split hi
__device__ float g_whlo[(size_t)HH * SIXH];      // 25 MB: Wh split lo
__device__ float g_hhi[MB * HH];
__device__ float g_hlo[MB * HH];
__device__ float g_h[MB * HH];
__device__ float g_c[MB * HH];
__device__ unsigned g_bar[2];                    // [0]=count, [1]=gen

// ---------------- helpers ---------------------------------------------------
__device__ __forceinline__ void f32_split_tf32(float x, float& hi, float& lo) {
    uint32_t u;
    asm("cvt.rna.tf32.f32 %0, %1;" : "=r"(u) : "f"(x));
    hi = __uint_as_float(u);
    float r = x - hi;
    asm("cvt.rna.tf32.f32 %0, %1;" : "=r"(u) : "f"(r));
    lo = __uint_as_float(u);
}

__device__ __forceinline__ void mma_tf32(float* d, const float* a, const float* b) {
    asm volatile(
        "mma.sync.aligned.m16n8k8.row.col.f32.tf32.tf32.f32 "
        "{%0,%1,%2,%3},{%4,%5,%6,%7},{%8,%9},{%0,%1,%2,%3};"
        : "+f"(d[0]), "+f"(d[1]), "+f"(d[2]), "+f"(d[3])
        : "r"(__float_as_uint(a[0])), "r"(__float_as_uint(a[1])),
          "r"(__float_as_uint(a[2])), "r"(__float_as_uint(a[3])),
          "r"(__float_as_uint(b[0])), "r"(__float_as_uint(b[1])));
}

__device__ __forceinline__ float sigm(float x) { return 1.0f / (1.0f + expf(-x)); }

__device__ __forceinline__ unsigned ld_acquire_gpu(unsigned* p) {
    unsigned v;
    asm volatile("ld.acquire.gpu.u32 %0, [%1];" : "=r"(v) : "l"(p) : "memory");
    return v;
}
__device__ __forceinline__ void st_release_gpu(unsigned* p, unsigned v) {
    asm volatile("st.release.gpu.u32 [%0], %1;" :: "l"(p), "r"(v) : "memory");
}

// software grid barrier (sense-reversal; acquire/release; BOUNDED spin so a
// missed release can never hang the container -- it completes with wrong
// output instead, which the harness can diagnose)
__device__ __forceinline__ void grid_barrier(int nblocks) {
    __syncthreads();                 // all threads of block done with pre-barrier work
    if (threadIdx.x == 0) {
        unsigned gen = ld_acquire_gpu(&g_bar[1]);
        __threadfence();             // publish this block's global writes
        unsigned arrived = atomicAdd(&g_bar[0], 1u);
        if (arrived == (unsigned)(nblocks - 1)) {
            g_bar[0] = 0u;           // reset strictly before release publish
            st_release_gpu(&g_bar[1], gen + 1u);
        } else {
            long long spins = 0;
            while (ld_acquire_gpu(&g_bar[1]) == gen) {
                __nanosleep(32);
                if (++spins > 200000000LL) break;   // ~tens of seconds; never hit normally
            }
        }
    }
    __syncthreads();                 // fan the release out to all threads
    __threadfence();
}

// ---------------- tf32 split prep kernel ------------------------------------
__global__ void __launch_bounds__(256) split_tf32_kernel(
    const float* __restrict__ src, float* __restrict__ hi, float* __restrict__ lo, int n) {
    int i = blockIdx.x * blockDim.x + threadIdx.x;
    if (i < n) {
        float h, l;
        f32_split_tf32(src[i], h, l);
        hi[i] = h;
        lo[i] = l;
    }
}

// ---------------- 3xTF32 GEMM for phase A: C = A[.,K]*B[K,6144] + bias ------
// Block tile 64x64, BK=16, 128 threads (4 warps, 2x2 warp grid, warp 32x32).
__global__ void __launch_bounds__(128) gemm3_tf32(
    const float* __restrict__ A, int lda, int K,
    const float* __restrict__ B,        // row-major [K, 6144]
    const float* __restrict__ bias,     // [6144]
    float* __restrict__ C)              // row-major [.,6144]
{
    __shared__ float As_hi[64][20], As_lo[64][20];
    __shared__ float Bs_hi[16][72], Bs_lo[16][72];

    const int tid = threadIdx.x;
    const int lane = tid & 31, warp = tid >> 5;
    const int wRow = warp >> 1, wCol = warp & 1;
    const int m0 = blockIdx.y * 64, n0 = blockIdx.x * 64;

    float acc[2][4][4];
#pragma unroll
    for (int mt = 0; mt < 2; mt++)
#pragma unroll
        for (int nt = 0; nt < 4; nt++)
#pragma unroll
            for (int i = 0; i < 4; i++) acc[mt][nt][i] = 0.0f;

    for (int k0 = 0; k0 < K; k0 += 16) {
#pragma unroll
        for (int r = 0; r < 2; r++) {
            int idx = tid + r * 128;
            int row = idx >> 2, kq = idx & 3;
            float4 v = *(const float4*)(A + (size_t)(m0 + row) * lda + k0 + kq * 4);
            float hi, lo;
            f32_split_tf32(v.x, hi, lo); As_hi[row][kq * 4 + 0] = hi; As_lo[row][kq * 4 + 0] = lo;
            f32_split_tf32(v.y, hi, lo); As_hi[row][kq * 4 + 1] = hi; As_lo[row][kq * 4 + 1] = lo;
            f32_split_tf32(v.z, hi, lo); As_hi[row][kq * 4 + 2] = hi; As_lo[row][kq * 4 + 2] = lo;
            f32_split_tf32(v.w, hi, lo); As_hi[row][kq * 4 + 3] = hi; As_lo[row][kq * 4 + 3] = lo;
        }
#pragma unroll
        for (int r = 0; r < 2; r++) {
            int idx = tid + r * 128;
            int row = idx >> 4, nq = idx & 15;
            float4 v = *(const float4*)(B + (size_t)(k0 + row) * SIXH + n0 + nq * 4);
            float hi, lo;
            f32_split_tf32(v.x, hi, lo); Bs_hi[row][nq * 4 + 0] = hi; Bs_lo[row][nq * 4 + 0] = lo;
            f32_split_tf32(v.y, hi, lo); Bs_hi[row][nq * 4 + 1] = hi; Bs_lo[row][nq * 4 + 1] = lo;
            f32_split_tf32(v.z, hi, lo); Bs_hi[row][nq * 4 + 2] = hi; Bs_lo[row][nq * 4 + 2] = lo;
            f32_split_tf32(v.w, hi, lo); Bs_hi[row][nq * 4 + 3] = hi; Bs_lo[row][nq * 4 + 3] = lo;
        }
        __syncthreads();

#pragma unroll
        for (int ks = 0; ks < 16; ks += 8) {
            float ahi[2][4], alo[2][4];
#pragma unroll
            for (int mt = 0; mt < 2; mt++) {
                int r0 = wRow * 32 + mt * 16 + (lane >> 2);
                int kk = ks + (lane & 3);
                ahi[mt][0] = As_hi[r0][kk];     ahi[mt][1] = As_hi[r0 + 8][kk];
                ahi[mt][2] = As_hi[r0][kk + 4]; ahi[mt][3] = As_hi[r0 + 8][kk + 4];
                alo[mt][0] = As_lo[r0][kk];     alo[mt][1] = As_lo[r0 + 8][kk];
                alo[mt][2] = As_lo[r0][kk + 4]; alo[mt][3] = As_lo[r0 + 8][kk + 4];
            }
            float bhi[4][2], blo[4][2];
#pragma unroll
            for (int nt = 0; nt < 4; nt++) {
                int nc = wCol * 32 + nt * 8 + (lane >> 2);
                int kk = ks + (lane & 3);
                bhi[nt][0] = Bs_hi[kk][nc]; bhi[nt][1] = Bs_hi[kk + 4][nc];
                blo[nt][0] = Bs_lo[kk][nc]; blo[nt][1] = Bs_lo[kk + 4][nc];
            }
#pragma unroll
            for (int mt = 0; mt < 2; mt++)
#pragma unroll
                for (int nt = 0; nt < 4; nt++) {
                    mma_tf32(acc[mt][nt], ahi[mt], bhi[nt]);
                    mma_tf32(acc[mt][nt], ahi[mt], blo[nt]);
                    mma_tf32(acc[mt][nt], alo[mt], bhi[nt]);
                }
        }
        __syncthreads();
    }

#pragma unroll
    for (int mt = 0; mt < 2; mt++) {
        int r0 = m0 + wRow * 32 + mt * 16 + (lane >> 2);
#pragma unroll
        for (int nt = 0; nt < 4; nt++) {
            int cc = n0 + wCol * 32 + nt * 8 + ((lane & 3) << 1);
            float* p0 = C + (size_t)r0 * SIXH + cc;
            float* p1 = p0 + (size_t)8 * SIXH;
            float b0 = bias[cc], b1 = bias[cc + 1];
            p0[0] = acc[mt][nt][0] + b0; p0[1] = acc[mt][nt][1] + b1;
            p1[0] = acc[mt][nt][2] + b0; p1[1] = acc[mt][nt][3] + b1;
        }
    }
}

// ---------------- persistent recurrence kernel ------------------------------
// 96 blocks x 256 threads. Per step:
//   phase 1: block b computes z[:, b*64 : b*64+64] += h @ Wh (3xTF32 mma)
//   barrier
//   phase 2: blocks 0..63: gate + cummax + state update for batch row m=b
//   barrier
__global__ void __launch_bounds__(256) recur_persist(
    const float* __restrict__ whhi, const float* __restrict__ whlo, // [1024,6144]
    float* __restrict__ xz,    // [T,64,6144]
    float* __restrict__ allh,  // [T,64,1024]
    float* __restrict__ hhi, float* __restrict__ hlo,   // [64,1024]
    float* __restrict__ hbuf, float* __restrict__ cbuf) // [64,1024]
{
    __shared__ float As_hi[64][20], As_lo[64][20];
    __shared__ float Bs_hi[16][68], Bs_lo[16][68];
    __shared__ float sa[8], sb[8];

    const int tid = threadIdx.x;
    const int lane = tid & 31, warp = tid >> 5;
    const int wRow = warp >> 2, wCol = warp & 3;   // 2 x 4 warp grid
    const int b = blockIdx.x;
    const int n0 = b * 64;
    const int NB = gridDim.x;

    // thread->tile-load mapping (constant across steps)
    const int arow = tid >> 2, akq = tid & 3;   // A: 64x16 via float4
    const int brow = tid >> 4, bnq = tid & 15;  // B: 16x64 via float4

    for (int t = 0; t < TT; t++) {
        float* zslice = xz + (size_t)t * MB * SIXH;

        // ---------------- phase 1: z tile += h @ Wh tile ----------------
        // warp tile: 32 rows x 16 cols  (wRow in {0,1}, wCol in {0..3})
        float acc[2][2][4];
#pragma unroll
        for (int mt = 0; mt < 2; mt++)
#pragma unroll
            for (int nt = 0; nt < 2; nt++)
#pragma unroll
                for (int i = 0; i < 4; i++) acc[mt][nt][i] = 0.0f;

        for (int k0 = 0; k0 < HH; k0 += 16) {
            // A tile: h splits (written by other blocks -> bypass L1 with ldcg)
            {
                const float4* pa = (const float4*)(hhi + (size_t)arow * HH + k0 + akq * 4);
                float4 v = __ldcg(pa);
                As_hi[arow][akq * 4 + 0] = v.x; As_hi[arow][akq * 4 + 1] = v.y;
                As_hi[arow][akq * 4 + 2] = v.z; As_hi[arow][akq * 4 + 3] = v.w;
                const float4* pl = (const float4*)(hlo + (size_t)arow * HH + k0 + akq * 4);
                float4 w = __ldcg(pl);
                As_lo[arow][akq * 4 + 0] = w.x; As_lo[arow][akq * 4 + 1] = w.y;
                As_lo[arow][akq * 4 + 2] = w.z; As_lo[arow][akq * 4 + 3] = w.w;
            }
            // B tile: Wh splits (read-only, prepped before launch)
            {
                float4 v = *(const float4*)(whhi + (size_t)(k0 + brow) * SIXH + n0 + bnq * 4);
                Bs_hi[brow][bnq * 4 + 0] = v.x; Bs_hi[brow][bnq * 4 + 1] = v.y;
                Bs_hi[brow][bnq * 4 + 2] = v.z; Bs_hi[brow][bnq * 4 + 3] = v.w;
                float4 w = *(const float4*)(whlo + (size_t)(k0 + brow) * SIXH + n0 + bnq * 4);
                Bs_lo[brow][bnq * 4 + 0] = w.x; Bs_lo[brow][bnq * 4 + 1] = w.y;
                Bs_lo[brow][bnq * 4 + 2] = w.z; Bs_lo[brow][bnq * 4 + 3] = w.w;
            }
            __syncthreads();

#pragma unroll
            for (int ks = 0; ks < 16; ks += 8) {
                float ahi[2][4], alo[2][4];
#pragma unroll
                for (int mt = 0; mt < 2; mt++) {
                    int r0 = wRow * 32 + mt * 16 + (lane >> 2);
                    int kk = ks + (lane & 3);
                    ahi[mt][0] = As_hi[r0][kk];     ahi[mt][1] = As_hi[r0 + 8][kk];
                    ahi[mt][2] = As_hi[r0][kk + 4]; ahi[mt][3] = As_hi[r0 + 8][kk + 4];
                    alo[mt][0] = As_lo[r0][kk];     alo[mt][1] = As_lo[r0 + 8][kk];
                    alo[mt][2] = As_lo[r0][kk + 4]; alo[mt][3] = As_lo[r0 + 8][kk + 4];
                }
                float bhi[2][2], blo[2][2];
#pragma unroll
                for (int nt = 0; nt < 2; nt++) {
                    int nc = wCol * 16 + nt * 8 + (lane >> 2);
                    int kk = ks + (lane & 3);
                    bhi[nt][0] = Bs_hi[kk][nc]; bhi[nt][1] = Bs_hi[kk + 4][nc];
                    blo[nt][0] = Bs_lo[kk][nc]; blo[nt][1] = Bs_lo[kk + 4][nc];
                }
#pragma unroll
                for (int mt = 0; mt < 2; mt++)
#pragma unroll
                    for (int nt = 0; nt < 2; nt++) {
                        mma_tf32(acc[mt][nt], ahi[mt], bhi[nt]);
                        mma_tf32(acc[mt][nt], ahi[mt], blo[nt]);
                        mma_tf32(acc[mt][nt], alo[mt], bhi[nt]);
                    }
            }
            __syncthreads();
        }

        // epilogue: z tile read-modify-write (only this block touches its cols)
#pragma unroll
        for (int mt = 0; mt < 2; mt++) {
            int r0 = wRow * 32 + mt * 16 + (lane >> 2);
#pragma unroll
            for (int nt = 0; nt < 2; nt++) {
                int cc = n0 + wCol * 16 + nt * 8 + ((lane & 3) << 1);
                float* p0 = zslice + (size_t)r0 * SIXH + cc;
                float* p1 = p0 + (size_t)8 * SIXH;
                p0[0] += acc[mt][nt][0]; p0[1] += acc[mt][nt][1];
                p1[0] += acc[mt][nt][2]; p1[1] += acc[mt][nt][3];
            }
        }

        grid_barrier(NB);

        // ---------------- phase 2: gate + cummax + state update ----------------
        if (b < MB) {
            const int m = b;
            const int wid = warp;
            const float* zr = zslice + (size_t)m * SIXH;

            float4 ft4 = __ldcg((const float4*)(zr + 4096 + tid * 4));
            float4 it4 = __ldcg((const float4*)(zr + 5120 + tid * 4));

            float mft = fmaxf(fmaxf(ft4.x, ft4.y), fmaxf(ft4.z, ft4.w));
            float mit = fmaxf(fmaxf(it4.x, it4.y), fmaxf(it4.z, it4.w));
#pragma unroll
            for (int o = 16; o > 0; o >>= 1) {
                mft = fmaxf(mft, __shfl_xor_sync(0xffffffffu, mft, o));
                mit = fmaxf(mit, __shfl_xor_sync(0xffffffffu, mit, o));
            }
            if (lane == 0) { sa[wid] = mft; sb[wid] = mit; }
            __syncthreads();
            mft = sa[0]; mit = sb[0];
#pragma unroll
            for (int w = 1; w < 8; w++) { mft = fmaxf(mft, sa[w]); mit = fmaxf(mit, sb[w]); }
            __syncthreads();

            float eft[4], eit[4], pft[4], pit[4];
            eft[0] = expf(ft4.x - mft); eft[1] = expf(ft4.y - mft);
            eft[2] = expf(ft4.z - mft); eft[3] = expf(ft4.w - mft);
            eit[0] = expf(it4.x - mit); eit[1] = expf(it4.y - mit);
            eit[2] = expf(it4.z - mit); eit[3] = expf(it4.w - mit);
            pft[0] = eft[0]; pit[0] = eit[0];
#pragma unroll
            for (int i = 1; i < 4; i++) { pft[i] = pft[i - 1] + eft[i]; pit[i] = pit[i - 1] + eit[i]; }
            float Sf = pft[3], Si = pit[3];

            float xf = Sf, xi = Si;
#pragma unroll
            for (int o = 1; o < 32; o <<= 1) {
                float a = __shfl_up_sync(0xffffffffu, xf, o);
                float bb = __shfl_up_sync(0xffffffffu, xi, o);
                if (lane >= o) { xf += a; xi += bb; }
            }
            if (lane == 31) { sa[wid] = xf; sb[wid] = xi; }
            __syncthreads();
            float basef = 0.0f, basei = 0.0f, totf = 0.0f, toti = 0.0f;
#pragma unroll
            for (int w = 0; w < 8; w++) {
                float va = sa[w], vb = sb[w];
                if (w < wid) { basef += va; basei += vb; }
                totf += va; toti += vb;
            }
            __syncthreads();
            float exclf = basef + xf - Sf;
            float excli = basei + xi - Si;
            float invf = 1.0f / totf, invi = 1.0f / toti;

            float4 zi4 = __ldcg((const float4*)(zr + tid * 4));
            float4 zf4 = __ldcg((const float4*)(zr + 1024 + tid * 4));
            float4 zg4 = __ldcg((const float4*)(zr + 2048 + tid * 4));
            float4 zo4 = __ldcg((const float4*)(zr + 3072 + tid * 4));
            float4 c4  = *(const float4*)(cbuf + (size_t)m * HH + tid * 4);

            float zi[4] = {zi4.x, zi4.y, zi4.z, zi4.w};
            float zf[4] = {zf4.x, zf4.y, zf4.z, zf4.w};
            float zg[4] = {zg4.x, zg4.y, zg4.z, zg4.w};
            float zo[4] = {zo4.x, zo4.y, zo4.z, zo4.w};
            float co[4] = {c4.x, c4.y, c4.z, c4.w};
            float hv[4], cv[4], hhi4[4], hlo4[4];
#pragma unroll
            for (int i = 0; i < 4; i++) {
                float ftil = (exclf + pft[i]) * invf;
                float itil = 1.0f - (excli + pit[i]) * invi;
                float f_t = sigm(zf[i]);
                float i_t = sigm(zi[i]);
                float o_t = sigm(zo[i]);
                float ch  = tanhf(zg[i]);
                float om  = ftil * itil;
                float fh  = f_t * om + (ftil - om);
                float ih  = i_t * om + (itil - om);
                float cn  = fh * co[i] + ih * ch;
                cv[i] = cn;
                hv[i] = o_t * tanhf(cn);
                f32_split_tf32(hv[i], hhi4[i], hlo4[i]);
            }
            size_t off = (size_t)m * HH + tid * 4;
            *(float4*)(cbuf + off) = make_float4(cv[0], cv[1], cv[2], cv[3]);
            *(float4*)(hbuf + off) = make_float4(hv[0], hv[1], hv[2], hv[3]);
            *(float4*)(allh + (size_t)t * MB * HH + off) =
                make_float4(hv[0], hv[1], hv[2], hv[3]);
            *(float4*)(hhi + off) = make_float4(hhi4[0], hhi4[1], hhi4[2], hhi4[3]);
            *(float4*)(hlo + off) = make_float4(hlo4[0], hlo4[1], hlo4[2], hlo4[3]);
        }

        grid_barrier(NB);
    }
}

// ---------------- launch ----------------------------------------------------
extern "C" void kernel_launch(void* const* d_in, const int* in_sizes, int n_in,
                              void* d_out, int out_size) {
    const float* X  = (const float*)d_in[0];   // [256,64,512]
    const float* W0 = (const float*)d_in[1];   // [1536,6144]
    const float* b0 = (const float*)d_in[2];   // [6144]
    const float* W1 = (const float*)d_in[3];   // [2048,6144]
    const float* b1 = (const float*)d_in[4];   // [6144]
    float* out = (float*)d_out;

    float *xz, *h0all, *whhi, *whlo, *hhi, *hlo, *h, *c;
    unsigned* bar;
    cudaGetSymbolAddress((void**)&xz, g_xz);
    cudaGetSymbolAddress((void**)&h0all, g_h0all);
    cudaGetSymbolAddress((void**)&whhi, g_whhi);
    cudaGetSymbolAddress((void**)&whlo, g_whlo);
    cudaGetSymbolAddress((void**)&hhi, g_hhi);
    cudaGetSymbolAddress((void**)&hlo, g_hlo);
    cudaGetSymbolAddress((void**)&h, g_h);
    cudaGetSymbolAddress((void**)&c, g_c);
    cudaGetSymbolAddress((void**)&bar, g_bar);

    const size_t ALLH = (size_t)TT * MB * HH;           // 16,777,216
    const size_t HN   = (size_t)2 * MB * HH;            // 131,072
    const size_t stateBytes = (size_t)MB * HH * sizeof(float);
    const int WHN = HH * SIXH;                          // 6,291,456

    dim3 bigGrid(96, 256);   // 6144/64 x 16384/64

    cudaMemsetAsync(bar, 0, 2 * sizeof(unsigned));

    // ---------------- layer 0 ----------------
    gemm3_tf32<<<bigGrid, 128>>>(X, DD, DD, W0, b0, xz);
    split_tf32_kernel<<<(WHN + 255) / 256, 256>>>(W0 + (size_t)DD * SIXH, whhi, whlo, WHN);
    cudaMemsetAsync(hhi, 0, stateBytes);
    cudaMemsetAsync(hlo, 0, stateBytes);
    cudaMemsetAsync(c, 0, stateBytes);
    recur_persist<<<96, 256>>>(whhi, whlo, xz, h0all, hhi, hlo, h, c);
    cudaMemcpyAsync(out + ALLH, h, stateBytes, cudaMemcpyDeviceToDevice);
    cudaMemcpyAsync(out + ALLH + HN, c, stateBytes, cudaMemcpyDeviceToDevice);

    // ---------------- layer 1 ----------------
    gemm3_tf32<<<bigGrid, 128>>>(h0all, HH, HH, W1, b1, xz);
    split_tf32_kernel<<<(WHN + 255) / 256, 256>>>(W1 + (size_t)HH * SIXH, whhi, whlo, WHN);
    cudaMemsetAsync(hhi, 0, stateBytes);
    cudaMemsetAsync(hlo, 0, stateBytes);
    cudaMemsetAsync(c, 0, stateBytes);
    recur_persist<<<96, 256>>>(whhi, whlo, xz, out, hhi, hlo, h, c);
    cudaMemcpyAsync(out + ALLH + (size_t)MB * HH, h, stateBytes, cudaMemcpyDeviceToDevice);
    cudaMemcpyAsync(out + ALLH + HN + (size_t)MB * HH, c, stateBytes, cudaMemcpyDeviceToDevice);
}

// round 13
// speedup vs baseline: 1.4895x; 1.4895x over previous
#include <cuda_runtime.h>
#include <cuda_bf16.h>
#include <cstdint>

#define SIXH 6144
#define TT 256
#define MB 64
#define HH 1024
#define DD 512
#define MTOT (TT * MB)   // 16384

// ---------------- scratch (device globals; no runtime allocation) ----------
__device__ float g_xz[(size_t)TT * MB * SIXH];     // 402 MB: z (row-major)
__device__ float g_af[(size_t)MTOT * HH * 2];      // 134 MB: A fragments (X or h0all), hi/lo
__device__ float g_wxf[(size_t)HH * SIXH * 2];     // 50 MB: B fragments Wx
__device__ float g_whf[(size_t)HH * SIXH * 2];     // 50 MB: B fragments Wh
__device__ float g_hf[MB * HH * 2];                // h fragments (hi/lo)
__device__ float g_h[MB * HH];
__device__ float g_c[MB * HH];
__device__ unsigned g_bar[2];                      // [0]=count, [1]=gen

// ---------------- helpers ---------------------------------------------------
__device__ __forceinline__ void f32_split_tf32(float x, float& hi, float& lo) {
    uint32_t u;
    asm("cvt.rna.tf32.f32 %0, %1;" : "=r"(u) : "f"(x));
    hi = __uint_as_float(u);
    float r = x - hi;
    asm("cvt.rna.tf32.f32 %0, %1;" : "=r"(u) : "f"(r));
    lo = __uint_as_float(u);
}

__device__ __forceinline__ void mma_tf32(float* d, const float* a, const float* b) {
    asm volatile(
        "mma.sync.aligned.m16n8k8.row.col.f32.tf32.tf32.f32 "
        "{%0,%1,%2,%3},{%4,%5,%6,%7},{%8,%9},{%0,%1,%2,%3};"
        : "+f"(d[0]), "+f"(d[1]), "+f"(d[2]), "+f"(d[3])
        : "r"(__float_as_uint(a[0])), "r"(__float_as_uint(a[1])),
          "r"(__float_as_uint(a[2])), "r"(__float_as_uint(a[3])),
          "r"(__float_as_uint(b[0])), "r"(__float_as_uint(b[1])));
}

__device__ __forceinline__ float sigm(float x) { return 1.0f / (1.0f + expf(-x)); }

__device__ __forceinline__ unsigned ld_acquire_gpu(unsigned* p) {
    unsigned v;
    asm volatile("ld.acquire.gpu.u32 %0, [%1];" : "=r"(v) : "l"(p) : "memory");
    return v;
}
__device__ __forceinline__ void st_release_gpu(unsigned* p, unsigned v) {
    asm volatile("st.release.gpu.u32 [%0], %1;" :: "l"(p), "r"(v) : "memory");
}

// software grid barrier (sense-reversal; acquire/release; bounded spin)
__device__ __forceinline__ void grid_barrier(int nblocks) {
    __syncthreads();
    if (threadIdx.x == 0) {
        unsigned gen = ld_acquire_gpu(&g_bar[1]);
        __threadfence();
        unsigned arrived = atomicAdd(&g_bar[0], 1u);
        if (arrived == (unsigned)(nblocks - 1)) {
            g_bar[0] = 0u;
            st_release_gpu(&g_bar[1], gen + 1u);
        } else {
            long long spins = 0;
            while (ld_acquire_gpu(&g_bar[1]) == gen) {
                __nanosleep(32);
                if (++spins > 200000000LL) break;
            }
        }
    }
    __syncthreads();
    __threadfence();
}

// ---------------- fragment-layout index helpers ------------------------------
// mma m16n8k8.row.col fragment maps:
//   A elem (m,k): lane=(m&7)*4+(k&3); reg=((m>>3)&1)+2*((k>>2)&1)
//   B elem (k,n): lane=(n&7)*4+(k&3); reg=(k>>2)&1
// A chunk (16m x 8k) = 256 floats: lane*8 + reg + 4*plane  (hi float4, lo float4)
// B chunk (8k x 8n)  = 128 floats: lane*4 + reg + 2*plane  (bhi0,bhi1,blo0,blo1)
__device__ __forceinline__ size_t a_frag_idx(int m, int k, int K, int plane) {
    size_t chunk = (size_t)(m >> 4) * (K >> 3) + (k >> 3);
    return chunk * 256 + (size_t)((m & 7) * 4 + (k & 3)) * 8 +
           ((m >> 3) & 1) + 2 * ((k >> 2) & 1) + 4 * plane;
}
__device__ __forceinline__ size_t b_frag_idx(int k, int n, int K, int plane) {
    size_t chunk = (size_t)(n >> 3) * (K >> 3) + (k >> 3);
    return chunk * 128 + (size_t)((n & 7) * 4 + (k & 3)) * 4 + ((k >> 2) & 1) + 2 * plane;
}

// ---------------- prep kernels ----------------------------------------------
__global__ void __launch_bounds__(256) prep_a_kernel(
    const float* __restrict__ src, float* __restrict__ dst, int M, int K) {
    size_t i = (size_t)blockIdx.x * blockDim.x + threadIdx.x;
    if (i >= (size_t)M * K) return;
    int m = (int)(i / K), k = (int)(i - (size_t)m * K);
    float hi, lo;
    f32_split_tf32(src[i], hi, lo);
    size_t base = a_frag_idx(m, k, K, 0);
    dst[base] = hi;
    dst[base + 4] = lo;
}
__global__ void __launch_bounds__(256) prep_b_kernel(
    const float* __restrict__ src, float* __restrict__ dst, int K) {
    size_t i = (size_t)blockIdx.x * blockDim.x + threadIdx.x;
    if (i >= (size_t)K * SIXH) return;
    int k = (int)(i / SIXH), n = (int)(i - (size_t)k * SIXH);
    float hi, lo;
    f32_split_tf32(src[i], hi, lo);
    size_t base = b_frag_idx(k, n, K, 0);
    dst[base] = hi;
    dst[base + 2] = lo;
}

// ---------------- phase-A GEMM: C = Afrag @ Bfrag + bias ---------------------
// block 64x64, 128 threads, warps 2x2 (warp tile 32x32), k-chunk 16, dbl-buffered
__global__ void __launch_bounds__(128) gemm_fragA(
    const float* __restrict__ Af, const float* __restrict__ Bf,
    const float* __restrict__ bias, float* __restrict__ C, int K)
{
    __shared__ float sA[2][2048];   // 8 A-chunks (4 msub x 2 kb) x 256
    __shared__ float sB[2][2048];   // 16 B-chunks (8 nb x 2 kb) x 128

    const int tid = threadIdx.x, lane = tid & 31, warp = tid >> 5;
    const int wRow = warp >> 1, wCol = warp & 1;
    const int m0 = blockIdx.y * 64, n0 = blockIdx.x * 64;
    const int mb0 = m0 >> 4, nb0 = n0 >> 3;
    const int Kc = K >> 3;
    const float4* A4 = (const float4*)Af;
    const float4* B4 = (const float4*)Bf;

    float acc[2][4][4];
#pragma unroll
    for (int mt = 0; mt < 2; mt++)
#pragma unroll
        for (int nt = 0; nt < 4; nt++)
#pragma unroll
            for (int i = 0; i < 4; i++) acc[mt][nt][i] = 0.0f;

    float4 ra[4], rb[4];
    auto ldA = [&](int k0) {
#pragma unroll
        for (int i = 0; i < 4; i++) {
            int j = tid + 128 * i;
            int cl = j >> 6;                 // 0..7
            int ms = cl >> 1, kb = cl & 1;
            size_t gc = (size_t)(mb0 + ms) * Kc + (k0 >> 3) + kb;
            ra[i] = __ldg(&A4[gc * 64 + (j & 63)]);
        }
    };
    auto ldB = [&](int k0) {
#pragma unroll
        for (int i = 0; i < 4; i++) {
            int j = tid + 128 * i;
            int cl = j >> 5;                 // 0..15
            int nb = cl >> 1, kb = cl & 1;
            size_t gc = (size_t)(nb0 + nb) * Kc + (k0 >> 3) + kb;
            rb[i] = __ldg(&B4[gc * 32 + (j & 31)]);
        }
    };
    auto sts = [&](int buf) {
#pragma unroll
        for (int i = 0; i < 4; i++) {
            ((float4*)sA[buf])[tid + 128 * i] = ra[i];
            ((float4*)sB[buf])[tid + 128 * i] = rb[i];
        }
    };

    ldA(0); ldB(0);
    sts(0);
    __syncthreads();

    const int nk = K >> 4;
    for (int ic = 0; ic < nk; ic++) {
        const int cur = ic & 1;
        if (ic + 1 < nk) { ldA((ic + 1) << 4); ldB((ic + 1) << 4); }

#pragma unroll
        for (int kb = 0; kb < 2; kb++) {
            float4 ahi[2], alo[2];
#pragma unroll
            for (int mt = 0; mt < 2; mt++) {
                const float4* p = (const float4*)&sA[cur][(((wRow * 2 + mt) * 2 + kb) << 8) + lane * 8];
                ahi[mt] = p[0];
                alo[mt] = p[1];
            }
            float4 bf[4];
#pragma unroll
            for (int nt = 0; nt < 4; nt++)
                bf[nt] = *(const float4*)&sB[cur][(((wCol * 4 + nt) * 2 + kb) << 7) + lane * 4];
#pragma unroll
            for (int mt = 0; mt < 2; mt++)
#pragma unroll
                for (int nt = 0; nt < 4; nt++) {
                    mma_tf32(acc[mt][nt], &ahi[mt].x, &bf[nt].x);
                    mma_tf32(acc[mt][nt], &ahi[mt].x, &bf[nt].z);
                    mma_tf32(acc[mt][nt], &alo[mt].x, &bf[nt].x);
                }
        }

        if (ic + 1 < nk) {
            __syncthreads();
            sts(cur ^ 1);
            __syncthreads();
        }
    }

    // epilogue with bias
#pragma unroll
    for (int mt = 0; mt < 2; mt++) {
        int r0 = m0 + wRow * 32 + mt * 16 + (lane >> 2);
#pragma unroll
        for (int nt = 0; nt < 4; nt++) {
            int cc = n0 + wCol * 32 + nt * 8 + ((lane & 3) << 1);
            float b0v = bias[cc], b1v = bias[cc + 1];
            float* p0 = C + (size_t)r0 * SIXH + cc;
            float* p1 = p0 + (size_t)8 * SIXH;
            p0[0] = acc[mt][nt][0] + b0v;
            p0[1] = acc[mt][nt][1] + b1v;
            p1[0] = acc[mt][nt][2] + b0v;
            p1[1] = acc[mt][nt][3] + b1v;
        }
    }
}

// ---------------- persistent recurrence kernel ------------------------------
// 96 blocks x 256 threads (8 warps, grid 4x2, warp tile 16x32), k-chunk 16.
__global__ void __launch_bounds__(256) recur_persist(
    const float* __restrict__ whf,   // B fragments [1024, 6144]
    float* __restrict__ xz,          // [T,64,6144] row-major
    float* __restrict__ out_rm,      // layer1: all_h row-major dst (or null)
    float* __restrict__ af,          // layer0: g_af fragment dst (or null)
    float* __restrict__ hf,          // [64,1024] fragments
    float* __restrict__ hbuf, float* __restrict__ cbuf)  // row-major [64,1024]
{
    __shared__ float sA[2][2048];
    __shared__ float sB[2][2048];
    __shared__ float sa[8], sb[8];

    const int tid = threadIdx.x, lane = tid & 31, warp = tid >> 5;
    const int wRow = warp >> 1, wCol = warp & 1;   // 4 x 2 warp grid
    const int b = blockIdx.x, n0 = b * 64, NB = gridDim.x;
    const int nb0 = n0 >> 3;
    const float4* W4 = (const float4*)whf;
    const float4* H4 = (const float4*)hf;

    for (int t = 0; t < TT; t++) {
        float* zslice = xz + (size_t)t * MB * SIXH;

        // ---------------- phase 1: z tile += h @ Wh tile ----------------
        float acc[4][4];
#pragma unroll
        for (int nt = 0; nt < 4; nt++)
#pragma unroll
            for (int i = 0; i < 4; i++) acc[nt][i] = 0.0f;

        float4 ra[2], rb[2];
        auto ldA = [&](int k0) {
#pragma unroll
            for (int i = 0; i < 2; i++) {
                int j = tid + 256 * i;
                int cl = j >> 6;               // 0..7
                int ms = cl >> 1, kb = cl & 1;
                size_t gc = (size_t)ms * 128 + (k0 >> 3) + kb;
                ra[i] = __ldcg(&H4[gc * 64 + (j & 63)]);   // L2 only: cross-block data
            }
        };
        auto ldB = [&](int k0) {
#pragma unroll
            for (int i = 0; i < 2; i++) {
                int j = tid + 256 * i;
                int cl = j >> 5;               // 0..15
                int nb = cl >> 1, kb = cl & 1;
                size_t gc = (size_t)(nb0 + nb) * 128 + (k0 >> 3) + kb;
                rb[i] = __ldg(&W4[gc * 32 + (j & 31)]);
            }
        };
        auto sts = [&](int buf) {
#pragma unroll
            for (int i = 0; i < 2; i++) {
                ((float4*)sA[buf])[tid + 256 * i] = ra[i];
                ((float4*)sB[buf])[tid + 256 * i] = rb[i];
            }
        };

        ldA(0); ldB(0);
        sts(0);
        __syncthreads();

        for (int ic = 0; ic < 64; ic++) {      // 1024/16
            const int cur = ic & 1;
            if (ic + 1 < 64) { ldA((ic + 1) << 4); ldB((ic + 1) << 4); }

#pragma unroll
            for (int kb = 0; kb < 2; kb++) {
                const float4* p = (const float4*)&sA[cur][(((wRow * 2 + kb)) << 8) + lane * 8];
                float4 ahi = p[0], alo = p[1];
                float4 bf[4];
#pragma unroll
                for (int nt = 0; nt < 4; nt++)
                    bf[nt] = *(const float4*)&sB[cur][(((wCol * 4 + nt) * 2 + kb) << 7) + lane * 4];
#pragma unroll
                for (int nt = 0; nt < 4; nt++) {
                    mma_tf32(acc[nt], &ahi.x, &bf[nt].x);
                    mma_tf32(acc[nt], &ahi.x, &bf[nt].z);
                    mma_tf32(acc[nt], &alo.x, &bf[nt].x);
                }
            }

            if (ic + 1 < 64) {
                __syncthreads();
                sts(cur ^ 1);
                __syncthreads();
            }
        }

        // epilogue: z tile += acc (only this block's columns)
        {
            int r0 = wRow * 16 + (lane >> 2);
#pragma unroll
            for (int nt = 0; nt < 4; nt++) {
                int cc = n0 + wCol * 32 + nt * 8 + ((lane & 3) << 1);
                float* p0 = zslice + (size_t)r0 * SIXH + cc;
                float* p1 = p0 + (size_t)8 * SIXH;
                p0[0] += acc[nt][0]; p0[1] += acc[nt][1];
                p1[0] += acc[nt][2]; p1[1] += acc[nt][3];
            }
        }

        grid_barrier(NB);

        // ---------------- phase 2: gate + cummax + state update ----------------
        if (b < MB) {
            const int m = b;
            const int wid = warp;
            const float* zr = zslice + (size_t)m * SIXH;

            float4 ft4 = __ldcg((const float4*)(zr + 4096 + tid * 4));
            float4 it4 = __ldcg((const float4*)(zr + 5120 + tid * 4));

            float mft = fmaxf(fmaxf(ft4.x, ft4.y), fmaxf(ft4.z, ft4.w));
            float mit = fmaxf(fmaxf(it4.x, it4.y), fmaxf(it4.z, it4.w));
#pragma unroll
            for (int o = 16; o > 0; o >>= 1) {
                mft = fmaxf(mft, __shfl_xor_sync(0xffffffffu, mft, o));
                mit = fmaxf(mit, __shfl_xor_sync(0xffffffffu, mit, o));
            }
            if (lane == 0) { sa[wid] = mft; sb[wid] = mit; }
            __syncthreads();
            mft = sa[0]; mit = sb[0];
#pragma unroll
            for (int w = 1; w < 8; w++) { mft = fmaxf(mft, sa[w]); mit = fmaxf(mit, sb[w]); }
            __syncthreads();

            float eft[4], eit[4], pft[4], pit[4];
            eft[0] = expf(ft4.x - mft); eft[1] = expf(ft4.y - mft);
            eft[2] = expf(ft4.z - mft); eft[3] = expf(ft4.w - mft);
            eit[0] = expf(it4.x - mit); eit[1] = expf(it4.y - mit);
            eit[2] = expf(it4.z - mit); eit[3] = expf(it4.w - mit);
            pft[0] = eft[0]; pit[0] = eit[0];
#pragma unroll
            for (int i = 1; i < 4; i++) { pft[i] = pft[i - 1] + eft[i]; pit[i] = pit[i - 1] + eit[i]; }
            float Sf = pft[3], Si = pit[3];

            float xf = Sf, xi = Si;
#pragma unroll
            for (int o = 1; o < 32; o <<= 1) {
                float a = __shfl_up_sync(0xffffffffu, xf, o);
                float bb = __shfl_up_sync(0xffffffffu, xi, o);
                if (lane >= o) { xf += a; xi += bb; }
            }
            if (lane == 31) { sa[wid] = xf; sb[wid] = xi; }
            __syncthreads();
            float basef = 0.0f, basei = 0.0f, totf = 0.0f, toti = 0.0f;
#pragma unroll
            for (int w = 0; w < 8; w++) {
                float va = sa[w], vb = sb[w];
                if (w < wid) { basef += va; basei += vb; }
                totf += va; toti += vb;
            }
            __syncthreads();
            float exclf = basef + xf - Sf;
            float excli = basei + xi - Si;
            float invf = 1.0f / totf, invi = 1.0f / toti;

            float4 zi4 = __ldcg((const float4*)(zr + tid * 4));
            float4 zf4 = __ldcg((const float4*)(zr + 1024 + tid * 4));
            float4 zg4 = __ldcg((const float4*)(zr + 2048 + tid * 4));
            float4 zo4 = __ldcg((const float4*)(zr + 3072 + tid * 4));
            float4 c4  = *(const float4*)(cbuf + (size_t)m * HH + tid * 4);

            float zi[4] = {zi4.x, zi4.y, zi4.z, zi4.w};
            float zf[4] = {zf4.x, zf4.y, zf4.z, zf4.w};
            float zg[4] = {zg4.x, zg4.y, zg4.z, zg4.w};
            float zo[4] = {zo4.x, zo4.y, zo4.z, zo4.w};
            float co[4] = {c4.x, c4.y, c4.z, c4.w};
            float hv[4], cv[4];
#pragma unroll
            for (int i = 0; i < 4; i++) {
                float ftil = (exclf + pft[i]) * invf;
                float itil = 1.0f - (excli + pit[i]) * invi;
                float f_t = sigm(zf[i]);
                float i_t = sigm(zi[i]);
                float o_t = sigm(zo[i]);
                float ch  = tanhf(zg[i]);
                float om  = ftil * itil;
                float fh  = f_t * om + (ftil - om);
                float ih  = i_t * om + (itil - om);
                float cn  = fh * co[i] + ih * ch;
                cv[i] = cn;
                hv[i] = o_t * tanhf(cn);
                // write h in fragment-split layout (for next step's phase 1)
                float hh, hl;
                f32_split_tf32(hv[i], hh, hl);
                int j = tid * 4 + i;
                size_t fb = a_frag_idx(m, j, HH, 0);
                hf[fb] = hh;
                hf[fb + 4] = hl;
                if (af) {   // layer 0: also write h0all fragments for layer-1 phase A
                    size_t fa = a_frag_idx(t * MB + m, j, HH, 0);
                    af[fa] = hh;
                    af[fa + 4] = hl;
                }
            }
            size_t off = (size_t)m * HH + tid * 4;
            *(float4*)(cbuf + off) = make_float4(cv[0], cv[1], cv[2], cv[3]);
            *(float4*)(hbuf + off) = make_float4(hv[0], hv[1], hv[2], hv[3]);
            if (out_rm)
                *(float4*)(out_rm + (size_t)t * MB * HH + off) =
                    make_float4(hv[0], hv[1], hv[2], hv[3]);
        }

        grid_barrier(NB);
    }
}

// ---------------- launch ----------------------------------------------------
extern "C" void kernel_launch(void* const* d_in, const int* in_sizes, int n_in,
                              void* d_out, int out_size) {
    const float* X  = (const float*)d_in[0];   // [256,64,512]
    const float* W0 = (const float*)d_in[1];   // [1536,6144]
    const float* b0 = (const float*)d_in[2];   // [6144]
    const float* W1 = (const float*)d_in[3];   // [2048,6144]
    const float* b1 = (const float*)d_in[4];   // [6144]
    float* out = (float*)d_out;

    float *xz, *af, *wxf, *whf, *hf, *h, *c;
    unsigned* bar;
    cudaGetSymbolAddress((void**)&xz, g_xz);
    cudaGetSymbolAddress((void**)&af, g_af);
    cudaGetSymbolAddress((void**)&wxf, g_wxf);
    cudaGetSymbolAddress((void**)&whf, g_whf);
    cudaGetSymbolAddress((void**)&hf, g_hf);
    cudaGetSymbolAddress((void**)&h, g_h);
    cudaGetSymbolAddress((void**)&c, g_c);
    cudaGetSymbolAddress((void**)&bar, g_bar);

    const size_t ALLH = (size_t)TT * MB * HH;            // 16,777,216
    const size_t HN   = (size_t)2 * MB * HH;             // 131,072
    const size_t stateBytes = (size_t)MB * HH * sizeof(float);
    const size_t hfBytes = (size_t)MB * HH * 2 * sizeof(float);

    dim3 bigGrid(96, 256);   // 6144/64 x 16384/64

    cudaMemsetAsync(bar, 0, 2 * sizeof(unsigned));

    // ---------------- layer 0 ----------------
    {
        size_t nA = (size_t)MTOT * DD;
        prep_a_kernel<<<(unsigned)((nA + 255) / 256), 256>>>(X, af, MTOT, DD);
        size_t nBx = (size_t)DD * SIXH;
        prep_b_kernel<<<(unsigned)((nBx + 255) / 256), 256>>>(W0, wxf, DD);
        size_t nBh = (size_t)HH * SIXH;
        prep_b_kernel<<<(unsigned)((nBh + 255) / 256), 256>>>(W0 + (size_t)DD * SIXH, whf, HH);

        gemm_fragA<<<bigGrid, 128>>>(af, wxf, b0, xz, DD);

        cudaMemsetAsync(hf, 0, hfBytes);
        cudaMemsetAsync(c, 0, stateBytes);
        recur_persist<<<96, 256>>>(whf, xz, nullptr, af, hf, h, c);

        cudaMemcpyAsync(out + ALLH, h, stateBytes, cudaMemcpyDeviceToDevice);
        cudaMemcpyAsync(out + ALLH + HN, c, stateBytes, cudaMemcpyDeviceToDevice);
    }

    // ---------------- layer 1 ----------------
    {
        size_t nBx = (size_t)HH * SIXH;
        prep_b_kernel<<<(unsigned)((nBx + 255) / 256), 256>>>(W1, wxf, HH);
        prep_b_kernel<<<(unsigned)((nBx + 255) / 256), 256>>>(W1 + (size_t)HH * SIXH, whf, HH);

        gemm_fragA<<<bigGrid, 128>>>(af, wxf, b1, xz, HH);

        cudaMemsetAsync(hf, 0, hfBytes);
        cudaMemsetAsync(c, 0, stateBytes);
        recur_persist<<<96, 256>>>(whf, xz, out, nullptr, hf, h, c);

        cudaMemcpyAsync(out + ALLH + (size_t)MB * HH, h, stateBytes, cudaMemcpyDeviceToDevice);
        cudaMemcpyAsync(out + ALLH + HN + (size_t)MB * HH, c, stateBytes, cudaMemcpyDeviceToDevice);
    }
}

// round 14
// speedup vs baseline: 2.1272x; 1.4281x over previous
#include <cuda_runtime.h>
#include <cuda_bf16.h>
#include <cstdint>

#define SIXH 6144
#define TT 256
#define MB 64
#define HH 1024
#define DD 512
#define MTOT (TT * MB)   // 16384

// ---------------- scratch (device globals; no runtime allocation) ----------
__device__ float g_xz[(size_t)TT * MB * SIXH];     // 402 MB: z (row-major)
__device__ float g_af[(size_t)MTOT * HH * 2];      // 134 MB: A fragments (X or h0all), hi/lo
__device__ float g_wxf[(size_t)HH * SIXH * 2];     // 50 MB: B fragments Wx
__device__ float g_whf[(size_t)HH * SIXH * 2];     // 50 MB: B fragments Wh
__device__ float g_hf[MB * HH * 2];                // h fragments (hi/lo)
__device__ float g_h[MB * HH];
__device__ float g_c[MB * HH];
__device__ unsigned g_bar[2];                      // [0]=count, [1]=gen

// ---------------- helpers ---------------------------------------------------
__device__ __forceinline__ void f32_split_tf32(float x, float& hi, float& lo) {
    uint32_t u;
    asm("cvt.rna.tf32.f32 %0, %1;" : "=r"(u) : "f"(x));
    hi = __uint_as_float(u);
    float r = x - hi;
    asm("cvt.rna.tf32.f32 %0, %1;" : "=r"(u) : "f"(r));
    lo = __uint_as_float(u);
}

__device__ __forceinline__ void mma_tf32(float* d, const float* a, const float* b) {
    asm volatile(
        "mma.sync.aligned.m16n8k8.row.col.f32.tf32.tf32.f32 "
        "{%0,%1,%2,%3},{%4,%5,%6,%7},{%8,%9},{%0,%1,%2,%3};"
        : "+f"(d[0]), "+f"(d[1]), "+f"(d[2]), "+f"(d[3])
        : "r"(__float_as_uint(a[0])), "r"(__float_as_uint(a[1])),
          "r"(__float_as_uint(a[2])), "r"(__float_as_uint(a[3])),
          "r"(__float_as_uint(b[0])), "r"(__float_as_uint(b[1])));
}

__device__ __forceinline__ float sigm(float x) { return 1.0f / (1.0f + expf(-x)); }

__device__ __forceinline__ unsigned ld_acquire_gpu(unsigned* p) {
    unsigned v;
    asm volatile("ld.acquire.gpu.u32 %0, [%1];" : "=r"(v) : "l"(p) : "memory");
    return v;
}
__device__ __forceinline__ void st_release_gpu(unsigned* p, unsigned v) {
    asm volatile("st.release.gpu.u32 [%0], %1;" :: "l"(p), "r"(v) : "memory");
}

// software grid barrier (sense-reversal; acquire/release; bounded spin)
__device__ __forceinline__ void grid_barrier(int nblocks) {
    __syncthreads();
    if (threadIdx.x == 0) {
        unsigned gen = ld_acquire_gpu(&g_bar[1]);
        __threadfence();
        unsigned arrived = atomicAdd(&g_bar[0], 1u);
        if (arrived == (unsigned)(nblocks - 1)) {
            g_bar[0] = 0u;
            st_release_gpu(&g_bar[1], gen + 1u);
        } else {
            long long spins = 0;
            while (ld_acquire_gpu(&g_bar[1]) == gen) {
                __nanosleep(32);
                if (++spins > 200000000LL) break;
            }
        }
    }
    __syncthreads();
    __threadfence();
}

// ---------------- fragment-layout index helpers ------------------------------
// mma m16n8k8.row.col fragment maps:
//   A elem (m,k): lane=(m&7)*4+(k&3); reg=((m>>3)&1)+2*((k>>2)&1)
//   B elem (k,n): lane=(n&7)*4+(k&3); reg=(k>>2)&1
// A chunk (16m x 8k) = 256 floats: lane*8 + reg + 4*plane (lane float4s: hi, lo)
// B chunk (8k x 8n)  = 128 floats: lane*4 + reg + 2*plane (lane float4: bhi0,bhi1,blo0,blo1)
__device__ __forceinline__ size_t a_frag_idx(int m, int k, int K, int plane) {
    size_t chunk = (size_t)(m >> 4) * (K >> 3) + (k >> 3);
    return chunk * 256 + (size_t)((m & 7) * 4 + (k & 3)) * 8 +
           ((m >> 3) & 1) + 2 * ((k >> 2) & 1) + 4 * plane;
}
__device__ __forceinline__ size_t b_frag_idx(int k, int n, int K, int plane) {
    size_t chunk = (size_t)(n >> 3) * (K >> 3) + (k >> 3);
    return chunk * 128 + (size_t)((n & 7) * 4 + (k & 3)) * 4 + ((k >> 2) & 1) + 2 * plane;
}

// ---------------- prep kernels ----------------------------------------------
__global__ void __launch_bounds__(256) prep_a_kernel(
    const float* __restrict__ src, float* __restrict__ dst, int M, int K) {
    size_t i = (size_t)blockIdx.x * blockDim.x + threadIdx.x;
    if (i >= (size_t)M * K) return;
    int m = (int)(i / K), k = (int)(i - (size_t)m * K);
    float hi, lo;
    f32_split_tf32(src[i], hi, lo);
    size_t base = a_frag_idx(m, k, K, 0);
    dst[base] = hi;
    dst[base + 4] = lo;
}
__global__ void __launch_bounds__(256) prep_b_kernel(
    const float* __restrict__ src, float* __restrict__ dst, int K) {
    size_t i = (size_t)blockIdx.x * blockDim.x + threadIdx.x;
    if (i >= (size_t)K * SIXH) return;
    int k = (int)(i / SIXH), n = (int)(i - (size_t)k * SIXH);
    float hi, lo;
    f32_split_tf32(src[i], hi, lo);
    size_t base = b_frag_idx(k, n, K, 0);
    dst[base] = hi;
    dst[base + 2] = lo;
}

// ---------------- phase-A GEMM: direct-LDG fragment GEMM --------------------
// block 64x64, 128 threads? -> 256 threads, 8 warps 4x2, warp tile 16x32.
// No shared memory: lanes LDG.128 their mma fragments straight from gmem.
struct SlotA { float4 aH[2], aL[2], bF[4][2]; };

__device__ __forceinline__ void ldslotA(
    SlotA& S, const float4* __restrict__ A4, const float4* __restrict__ B4,
    size_t aBase, size_t bBase, int Kc, int kc0, int lane)
{
#pragma unroll
    for (int kb = 0; kb < 2; kb++) {
        size_t ac = (aBase + kc0 + kb) * 64 + lane * 2;
        S.aH[kb] = __ldg(&A4[ac]);
        S.aL[kb] = __ldg(&A4[ac + 1]);
    }
#pragma unroll
    for (int nt = 0; nt < 4; nt++)
#pragma unroll
        for (int kb = 0; kb < 2; kb++)
            S.bF[nt][kb] = __ldg(&B4[(bBase + (size_t)nt * Kc + kc0 + kb) * 32 + lane]);
}
__device__ __forceinline__ void mmaslotA(const SlotA& S, float acc[4][4]) {
#pragma unroll
    for (int kb = 0; kb < 2; kb++)
#pragma unroll
        for (int nt = 0; nt < 4; nt++) {
            mma_tf32(acc[nt], &S.aH[kb].x, &S.bF[nt][kb].x);
            mma_tf32(acc[nt], &S.aH[kb].x, &S.bF[nt][kb].z);
            mma_tf32(acc[nt], &S.aL[kb].x, &S.bF[nt][kb].x);
        }
}

__global__ void __launch_bounds__(256) gemm_fragA(
    const float* __restrict__ Af, const float* __restrict__ Bf,
    const float* __restrict__ bias, float* __restrict__ C, int K)
{
    const int tid = threadIdx.x, lane = tid & 31, warp = tid >> 5;
    const int wRow = warp >> 1, wCol = warp & 1;
    const int m0 = blockIdx.y * 64, n0 = blockIdx.x * 64;
    const int Kc = K >> 3;
    const float4* A4 = (const float4*)Af;
    const float4* B4 = (const float4*)Bf;
    const size_t aBase = (size_t)((m0 >> 4) + wRow) * Kc;
    const size_t bBase = (size_t)((n0 >> 3) + wCol * 4) * Kc;

    float acc[4][4];
#pragma unroll
    for (int nt = 0; nt < 4; nt++)
#pragma unroll
        for (int i = 0; i < 4; i++) acc[nt][i] = 0.0f;

    SlotA s0, s1;
    ldslotA(s0, A4, B4, aBase, bBase, Kc, 0, lane);

    const int nk = K >> 4;   // k-chunk 16 = 2 frag chunks; nk is even (32 or 64)
    for (int ic = 0; ic < nk; ic += 2) {
        if (ic + 1 < nk) ldslotA(s1, A4, B4, aBase, bBase, Kc, (ic + 1) * 2, lane);
        mmaslotA(s0, acc);
        if (ic + 2 < nk) ldslotA(s0, A4, B4, aBase, bBase, Kc, (ic + 2) * 2, lane);
        mmaslotA(s1, acc);
    }

    // epilogue with bias: warp tile rows m0+wRow*16, cols n0+wCol*32+nt*8
    const int r0 = m0 + wRow * 16 + (lane >> 2);
#pragma unroll
    for (int nt = 0; nt < 4; nt++) {
        int cc = n0 + wCol * 32 + nt * 8 + ((lane & 3) << 1);
        float b0v = __ldg(&bias[cc]), b1v = __ldg(&bias[cc + 1]);
        float* p0 = C + (size_t)r0 * SIXH + cc;
        float* p1 = p0 + (size_t)8 * SIXH;
        p0[0] = acc[nt][0] + b0v;
        p0[1] = acc[nt][1] + b1v;
        p1[0] = acc[nt][2] + b0v;
        p1[1] = acc[nt][3] + b1v;
    }
}

// ---------------- persistent recurrence kernel ------------------------------
// 128 blocks x 256 threads. Block b owns 48 z-columns. Per step:
//   phase 1: z[:, b*48 .. b*48+48) += h @ Wh  (direct-LDG fragment mma, kc=32)
//   barrier
//   phase 2: blocks 0..63: gate + cummax + state update for batch row m=b
//   barrier
struct SlotR { float4 aH[4], aL[4], bF[3][4]; };

__device__ __forceinline__ void ldslotR(
    SlotR& S, const float4* __restrict__ H4, const float4* __restrict__ W4,
    int aChunkRow, size_t bBase, int kc0, int lane)
{
#pragma unroll
    for (int kb = 0; kb < 4; kb++) {
        size_t ac = ((size_t)aChunkRow * 128 + kc0 + kb) * 64 + lane * 2;
        S.aH[kb] = __ldcg(&H4[ac]);       // h changes every step: L2 only
        S.aL[kb] = __ldcg(&H4[ac + 1]);
    }
#pragma unroll
    for (int nt = 0; nt < 3; nt++)
#pragma unroll
        for (int kb = 0; kb < 4; kb++)
            S.bF[nt][kb] = __ldg(&W4[(bBase + (size_t)nt * 128 + kc0 + kb) * 32 + lane]);
}
__device__ __forceinline__ void mmaslotR(const SlotR& S, float acc[3][4]) {
#pragma unroll
    for (int kb = 0; kb < 4; kb++)
#pragma unroll
        for (int nt = 0; nt < 3; nt++) {
            mma_tf32(acc[nt], &S.aH[kb].x, &S.bF[nt][kb].x);
            mma_tf32(acc[nt], &S.aH[kb].x, &S.bF[nt][kb].z);
            mma_tf32(acc[nt], &S.aL[kb].x, &S.bF[nt][kb].x);
        }
}

__global__ void __launch_bounds__(256) recur_persist(
    const float* __restrict__ whf,   // B fragments [1024, 6144]
    float* __restrict__ xz,          // [T,64,6144] row-major
    float* __restrict__ out_rm,      // layer1: all_h row-major dst (or null)
    float* __restrict__ af,          // layer0: fragment dst for layer-1 A (or null)
    float* __restrict__ hf,          // [64,1024] h fragments
    float* __restrict__ hbuf, float* __restrict__ cbuf)  // row-major [64,1024]
{
    __shared__ float sa[8], sb[8];

    const int tid = threadIdx.x, lane = tid & 31, warp = tid >> 5;
    const int wRow = warp >> 1, wCol = warp & 1;   // 4x2 warp grid; warp tile 16x24
    const int b = blockIdx.x, n0 = b * 48, NB = gridDim.x;
    const float4* W4 = (const float4*)whf;
    const float4* H4 = (const float4*)hf;
    const size_t bBase = (size_t)((n0 >> 3) + wCol * 3) * 128;

    for (int t = 0; t < TT; t++) {
        float* zslice = xz + (size_t)t * MB * SIXH;

        // ---------------- phase 1: z tile += h @ Wh tile ----------------
        float acc[3][4];
#pragma unroll
        for (int nt = 0; nt < 3; nt++)
#pragma unroll
            for (int i = 0; i < 4; i++) acc[nt][i] = 0.0f;

        SlotR s0, s1;
        ldslotR(s0, H4, W4, wRow, bBase, 0, lane);

        // 32 iters of k-chunk 32 (4 frag chunks); manual unroll-by-2 pipeline
        for (int ic = 0; ic < 32; ic += 2) {
            if (ic + 1 < 32) ldslotR(s1, H4, W4, wRow, bBase, (ic + 1) * 4, lane);
            mmaslotR(s0, acc);
            if (ic + 2 < 32) ldslotR(s0, H4, W4, wRow, bBase, (ic + 2) * 4, lane);
            mmaslotR(s1, acc);
        }

        // epilogue: z tile += acc (only this block's columns)
        {
            int r0 = wRow * 16 + (lane >> 2);
#pragma unroll
            for (int nt = 0; nt < 3; nt++) {
                int cc = n0 + wCol * 24 + nt * 8 + ((lane & 3) << 1);
                float* p0 = zslice + (size_t)r0 * SIXH + cc;
                float* p1 = p0 + (size_t)8 * SIXH;
                p0[0] += acc[nt][0]; p0[1] += acc[nt][1];
                p1[0] += acc[nt][2]; p1[1] += acc[nt][3];
            }
        }

        grid_barrier(NB);

        // ---------------- phase 2: gate + cummax + state update ----------------
        if (b < MB) {
            const int m = b;
            const int wid = warp;
            const float* zr = zslice + (size_t)m * SIXH;

            float4 ft4 = __ldcg((const float4*)(zr + 4096 + tid * 4));
            float4 it4 = __ldcg((const float4*)(zr + 5120 + tid * 4));

            float mft = fmaxf(fmaxf(ft4.x, ft4.y), fmaxf(ft4.z, ft4.w));
            float mit = fmaxf(fmaxf(it4.x, it4.y), fmaxf(it4.z, it4.w));
#pragma unroll
            for (int o = 16; o > 0; o >>= 1) {
                mft = fmaxf(mft, __shfl_xor_sync(0xffffffffu, mft, o));
                mit = fmaxf(mit, __shfl_xor_sync(0xffffffffu, mit, o));
            }
            if (lane == 0) { sa[wid] = mft; sb[wid] = mit; }
            __syncthreads();
            mft = sa[0]; mit = sb[0];
#pragma unroll
            for (int w = 1; w < 8; w++) { mft = fmaxf(mft, sa[w]); mit = fmaxf(mit, sb[w]); }
            __syncthreads();

            float eft[4], eit[4], pft[4], pit[4];
            eft[0] = expf(ft4.x - mft); eft[1] = expf(ft4.y - mft);
            eft[2] = expf(ft4.z - mft); eft[3] = expf(ft4.w - mft);
            eit[0] = expf(it4.x - mit); eit[1] = expf(it4.y - mit);
            eit[2] = expf(it4.z - mit); eit[3] = expf(it4.w - mit);
            pft[0] = eft[0]; pit[0] = eit[0];
#pragma unroll
            for (int i = 1; i < 4; i++) { pft[i] = pft[i - 1] + eft[i]; pit[i] = pit[i - 1] + eit[i]; }
            float Sf = pft[3], Si = pit[3];

            float xf = Sf, xi = Si;
#pragma unroll
            for (int o = 1; o < 32; o <<= 1) {
                float a = __shfl_up_sync(0xffffffffu, xf, o);
                float bb = __shfl_up_sync(0xffffffffu, xi, o);
                if (lane >= o) { xf += a; xi += bb; }
            }
            if (lane == 31) { sa[wid] = xf; sb[wid] = xi; }
            __syncthreads();
            float basef = 0.0f, basei = 0.0f, totf = 0.0f, toti = 0.0f;
#pragma unroll
            for (int w = 0; w < 8; w++) {
                float va = sa[w], vb = sb[w];
                if (w < wid) { basef += va; basei += vb; }
                totf += va; toti += vb;
            }
            __syncthreads();
            float exclf = basef + xf - Sf;
            float excli = basei + xi - Si;
            float invf = 1.0f / totf, invi = 1.0f / toti;

            float4 zi4 = __ldcg((const float4*)(zr + tid * 4));
            float4 zf4 = __ldcg((const float4*)(zr + 1024 + tid * 4));
            float4 zg4 = __ldcg((const float4*)(zr + 2048 + tid * 4));
            float4 zo4 = __ldcg((const float4*)(zr + 3072 + tid * 4));
            float4 c4  = *(const float4*)(cbuf + (size_t)m * HH + tid * 4);

            float zi[4] = {zi4.x, zi4.y, zi4.z, zi4.w};
            float zf[4] = {zf4.x, zf4.y, zf4.z, zf4.w};
            float zg[4] = {zg4.x, zg4.y, zg4.z, zg4.w};
            float zo[4] = {zo4.x, zo4.y, zo4.z, zo4.w};
            float co[4] = {c4.x, c4.y, c4.z, c4.w};
            float hv[4], cv[4];
#pragma unroll
            for (int i = 0; i < 4; i++) {
                float ftil = (exclf + pft[i]) * invf;
                float itil = 1.0f - (excli + pit[i]) * invi;
                float f_t = sigm(zf[i]);
                float i_t = sigm(zi[i]);
                float o_t = sigm(zo[i]);
                float ch  = tanhf(zg[i]);
                float om  = ftil * itil;
                float fh  = f_t * om + (ftil - om);
                float ih  = i_t * om + (itil - om);
                float cn  = fh * co[i] + ih * ch;
                cv[i] = cn;
                hv[i] = o_t * tanhf(cn);
                // write h in fragment-split layout (for next step's phase 1)
                float hh, hl;
                f32_split_tf32(hv[i], hh, hl);
                int j = tid * 4 + i;
                size_t fb = a_frag_idx(m, j, HH, 0);
                hf[fb] = hh;
                hf[fb + 4] = hl;
                if (af) {   // layer 0: also write h0all fragments for layer-1 phase A
                    size_t fa = a_frag_idx(t * MB + m, j, HH, 0);
                    af[fa] = hh;
                    af[fa + 4] = hl;
                }
            }
            size_t off = (size_t)m * HH + tid * 4;
            *(float4*)(cbuf + off) = make_float4(cv[0], cv[1], cv[2], cv[3]);
            *(float4*)(hbuf + off) = make_float4(hv[0], hv[1], hv[2], hv[3]);
            if (out_rm)
                *(float4*)(out_rm + (size_t)t * MB * HH + off) =
                    make_float4(hv[0], hv[1], hv[2], hv[3]);
        }

        grid_barrier(NB);
    }
}

// ---------------- launch ----------------------------------------------------
extern "C" void kernel_launch(void* const* d_in, const int* in_sizes, int n_in,
                              void* d_out, int out_size) {
    const float* X  = (const float*)d_in[0];   // [256,64,512]
    const float* W0 = (const float*)d_in[1];   // [1536,6144]
    const float* b0 = (const float*)d_in[2];   // [6144]
    const float* W1 = (const float*)d_in[3];   // [2048,6144]
    const float* b1 = (const float*)d_in[4];   // [6144]
    float* out = (float*)d_out;

    float *xz, *af, *wxf, *whf, *hf, *h, *c;
    unsigned* bar;
    cudaGetSymbolAddress((void**)&xz, g_xz);
    cudaGetSymbolAddress((void**)&af, g_af);
    cudaGetSymbolAddress((void**)&wxf, g_wxf);
    cudaGetSymbolAddress((void**)&whf, g_whf);
    cudaGetSymbolAddress((void**)&hf, g_hf);
    cudaGetSymbolAddress((void**)&h, g_h);
    cudaGetSymbolAddress((void**)&c, g_c);
    cudaGetSymbolAddress((void**)&bar, g_bar);

    const size_t ALLH = (size_t)TT * MB * HH;            // 16,777,216
    const size_t HN   = (size_t)2 * MB * HH;             // 131,072
    const size_t stateBytes = (size_t)MB * HH * sizeof(float);
    const size_t hfBytes = (size_t)MB * HH * 2 * sizeof(float);

    dim3 bigGrid(96, 256);   // 6144/64 x 16384/64

    cudaMemsetAsync(bar, 0, 2 * sizeof(unsigned));

    // ---------------- layer 0 ----------------
    {
        size_t nA = (size_t)MTOT * DD;
        prep_a_kernel<<<(unsigned)((nA + 255) / 256), 256>>>(X, af, MTOT, DD);
        size_t nBx = (size_t)DD * SIXH;
        prep_b_kernel<<<(unsigned)((nBx + 255) / 256), 256>>>(W0, wxf, DD);
        size_t nBh = (size_t)HH * SIXH;
        prep_b_kernel<<<(unsigned)((nBh + 255) / 256), 256>>>(W0 + (size_t)DD * SIXH, whf, HH);

        gemm_fragA<<<bigGrid, 256>>>(af, wxf, b0, xz, DD);

        cudaMemsetAsync(hf, 0, hfBytes);
        cudaMemsetAsync(c, 0, stateBytes);
        recur_persist<<<128, 256>>>(whf, xz, nullptr, af, hf, h, c);

        cudaMemcpyAsync(out + ALLH, h, stateBytes, cudaMemcpyDeviceToDevice);
        cudaMemcpyAsync(out + ALLH + HN, c, stateBytes, cudaMemcpyDeviceToDevice);
    }

    // ---------------- layer 1 ----------------
    {
        size_t nBx = (size_t)HH * SIXH;
        prep_b_kernel<<<(unsigned)((nBx + 255) / 256), 256>>>(W1, wxf, HH);
        prep_b_kernel<<<(unsigned)((nBx + 255) / 256), 256>>>(W1 + (size_t)HH * SIXH, whf, HH);

        gemm_fragA<<<bigGrid, 256>>>(af, wxf, b1, xz, HH);

        cudaMemsetAsync(hf, 0, hfBytes);
        cudaMemsetAsync(c, 0, stateBytes);
        recur_persist<<<128, 256>>>(whf, xz, out, nullptr, hf, h, c);

        cudaMemcpyAsync(out + ALLH + (size_t)MB * HH, h, stateBytes, cudaMemcpyDeviceToDevice);
        cudaMemcpyAsync(out + ALLH + HN + (size_t)MB * HH, c, stateBytes, cudaMemcpyDeviceToDevice);
    }
}

// round 15
// speedup vs baseline: 2.4821x; 1.1668x over previous
#include <cuda_runtime.h>
#include <cuda_bf16.h>
#include <cstdint>

#define SIXH 6144
#define TT 256
#define MB 64
#define HH 1024
#define DD 512
#define MTOT (TT * MB)   // 16384

// ---------------- scratch (device globals; no runtime allocation) ----------
__device__ float g_xz[(size_t)TT * MB * SIXH];     // 402 MB: z (row-major)
__device__ float g_af[(size_t)MTOT * HH * 2];      // 134 MB: A split-fragments (X or h0all)
__device__ float g_wxf[(size_t)HH * SIXH * 2];     // 50 MB: B split-fragments Wx
__device__ float g_whf[(size_t)HH * SIXH * 2];     // 50 MB: B split-fragments Wh
__device__ float g_hf[MB * HH];                    // h f32 fragments (split in-reg)
__device__ float g_h[MB * HH];
__device__ float g_c[MB * HH];
__device__ unsigned g_bar[2];                      // [0]=count, [1]=gen

// ---------------- helpers ---------------------------------------------------
__device__ __forceinline__ void f32_split_tf32(float x, float& hi, float& lo) {
    uint32_t u;
    asm("cvt.rna.tf32.f32 %0, %1;" : "=r"(u) : "f"(x));
    hi = __uint_as_float(u);
    float r = x - hi;
    asm("cvt.rna.tf32.f32 %0, %1;" : "=r"(u) : "f"(r));
    lo = __uint_as_float(u);
}

__device__ __forceinline__ void mma_tf32(float* d, const float* a, const float* b) {
    asm volatile(
        "mma.sync.aligned.m16n8k8.row.col.f32.tf32.tf32.f32 "
        "{%0,%1,%2,%3},{%4,%5,%6,%7},{%8,%9},{%0,%1,%2,%3};"
        : "+f"(d[0]), "+f"(d[1]), "+f"(d[2]), "+f"(d[3])
        : "r"(__float_as_uint(a[0])), "r"(__float_as_uint(a[1])),
          "r"(__float_as_uint(a[2])), "r"(__float_as_uint(a[3])),
          "r"(__float_as_uint(b[0])), "r"(__float_as_uint(b[1])));
}

__device__ __forceinline__ float sigm(float x) { return 1.0f / (1.0f + expf(-x)); }

__device__ __forceinline__ unsigned ld_acquire_gpu(unsigned* p) {
    unsigned v;
    asm volatile("ld.acquire.gpu.u32 %0, [%1];" : "=r"(v) : "l"(p) : "memory");
    return v;
}
__device__ __forceinline__ void st_release_gpu(unsigned* p, unsigned v) {
    asm volatile("st.release.gpu.u32 [%0], %1;" :: "l"(p), "r"(v) : "memory");
}

// software grid barrier (sense-reversal; acquire/release; bounded spin)
__device__ __forceinline__ void grid_barrier(int nblocks) {
    __syncthreads();
    if (threadIdx.x == 0) {
        unsigned gen = ld_acquire_gpu(&g_bar[1]);
        __threadfence();
        unsigned arrived = atomicAdd(&g_bar[0], 1u);
        if (arrived == (unsigned)(nblocks - 1)) {
            g_bar[0] = 0u;
            st_release_gpu(&g_bar[1], gen + 1u);
        } else {
            long long spins = 0;
            while (ld_acquire_gpu(&g_bar[1]) == gen) {
                __nanosleep(32);
                if (++spins > 200000000LL) break;
            }
        }
    }
    __syncthreads();
    __threadfence();
}

// ---------------- fragment-layout index helpers ------------------------------
// Split A chunk (16m x 8k) = 256 floats: lane*8 + reg + 4*plane (float4 hi, float4 lo)
// Split B chunk (8k x 8n)  = 128 floats: lane*4 + reg + 2*plane (bhi0,bhi1,blo0,blo1)
// f32   A chunk (16m x 8k) = 128 floats: lane*4 + reg           (float4 a0..a3)
__device__ __forceinline__ size_t a_frag_idx(int m, int k, int K, int plane) {
    size_t chunk = (size_t)(m >> 4) * (K >> 3) + (k >> 3);
    return chunk * 256 + (size_t)((m & 7) * 4 + (k & 3)) * 8 +
           ((m >> 3) & 1) + 2 * ((k >> 2) & 1) + 4 * plane;
}
__device__ __forceinline__ size_t b_frag_idx(int k, int n, int K, int plane) {
    size_t chunk = (size_t)(n >> 3) * (K >> 3) + (k >> 3);
    return chunk * 128 + (size_t)((n & 7) * 4 + (k & 3)) * 4 + ((k >> 2) & 1) + 2 * plane;
}

// ---------------- prep kernels ----------------------------------------------
__global__ void __launch_bounds__(256) prep_a_kernel(
    const float* __restrict__ src, float* __restrict__ dst, int M, int K) {
    size_t i = (size_t)blockIdx.x * blockDim.x + threadIdx.x;
    if (i >= (size_t)M * K) return;
    int m = (int)(i / K), k = (int)(i - (size_t)m * K);
    float hi, lo;
    f32_split_tf32(src[i], hi, lo);
    size_t base = a_frag_idx(m, k, K, 0);
    dst[base] = hi;
    dst[base + 4] = lo;
}
__global__ void __launch_bounds__(256) prep_b_kernel(
    const float* __restrict__ src, float* __restrict__ dst, int K) {
    size_t i = (size_t)blockIdx.x * blockDim.x + threadIdx.x;
    if (i >= (size_t)K * SIXH) return;
    int k = (int)(i / SIXH), n = (int)(i - (size_t)k * SIXH);
    float hi, lo;
    f32_split_tf32(src[i], hi, lo);
    size_t base = b_frag_idx(k, n, K, 0);
    dst[base] = hi;
    dst[base + 2] = lo;
}

// ---------------- phase-A GEMM: direct-LDG fragment GEMM --------------------
// block 128m x 64n, 256 threads, warps 4x2, warp tile 32m x 32n (M=2, N=4).
struct SlotP { float4 aH[2][2], aL[2][2], bF[4][2]; };

__device__ __forceinline__ void ldslotP(
    SlotP& S, const float4* __restrict__ A4, const float4* __restrict__ B4,
    size_t aBase0, size_t aBase1, size_t bBase, int Kc, int kc0, int lane)
{
#pragma unroll
    for (int kb = 0; kb < 2; kb++) {
        size_t ac0 = (aBase0 + kc0 + kb) * 64 + lane * 2;
        S.aH[0][kb] = __ldg(&A4[ac0]);
        S.aL[0][kb] = __ldg(&A4[ac0 + 1]);
        size_t ac1 = (aBase1 + kc0 + kb) * 64 + lane * 2;
        S.aH[1][kb] = __ldg(&A4[ac1]);
        S.aL[1][kb] = __ldg(&A4[ac1 + 1]);
    }
#pragma unroll
    for (int nt = 0; nt < 4; nt++)
#pragma unroll
        for (int kb = 0; kb < 2; kb++)
            S.bF[nt][kb] = __ldg(&B4[(bBase + (size_t)nt * Kc + kc0 + kb) * 32 + lane]);
}
__device__ __forceinline__ void mmaslotP(const SlotP& S, float acc[2][4][4]) {
#pragma unroll
    for (int kb = 0; kb < 2; kb++)
#pragma unroll
        for (int mt = 0; mt < 2; mt++)
#pragma unroll
            for (int nt = 0; nt < 4; nt++) {
                mma_tf32(acc[mt][nt], &S.aH[mt][kb].x, &S.bF[nt][kb].x);
                mma_tf32(acc[mt][nt], &S.aH[mt][kb].x, &S.bF[nt][kb].z);
                mma_tf32(acc[mt][nt], &S.aL[mt][kb].x, &S.bF[nt][kb].x);
            }
}

__global__ void __launch_bounds__(256) gemm_fragA(
    const float* __restrict__ Af, const float* __restrict__ Bf,
    const float* __restrict__ bias, float* __restrict__ C, int K)
{
    const int tid = threadIdx.x, lane = tid & 31, warp = tid >> 5;
    const int wRow = warp >> 1, wCol = warp & 1;
    const int m0 = blockIdx.y * 128, n0 = blockIdx.x * 64;
    const int Kc = K >> 3;
    const float4* A4 = (const float4*)Af;
    const float4* B4 = (const float4*)Bf;
    const size_t aBase0 = (size_t)((m0 >> 4) + wRow * 2) * Kc;
    const size_t aBase1 = aBase0 + Kc;   // next m-chunk row
    const size_t bBase = (size_t)((n0 >> 3) + wCol * 4) * Kc;

    float acc[2][4][4];
#pragma unroll
    for (int mt = 0; mt < 2; mt++)
#pragma unroll
        for (int nt = 0; nt < 4; nt++)
#pragma unroll
            for (int i = 0; i < 4; i++) acc[mt][nt][i] = 0.0f;

    SlotP s0, s1;
    ldslotP(s0, A4, B4, aBase0, aBase1, bBase, Kc, 0, lane);

    const int nk = K >> 4;   // k16 slots (32 or 64; even)
    for (int ic = 0; ic < nk; ic += 2) {
        ldslotP(s1, A4, B4, aBase0, aBase1, bBase, Kc, (ic + 1) * 2, lane);
        mmaslotP(s0, acc);
        if (ic + 2 < nk) ldslotP(s0, A4, B4, aBase0, aBase1, bBase, Kc, (ic + 2) * 2, lane);
        mmaslotP(s1, acc);
    }

    // epilogue with bias
#pragma unroll
    for (int mt = 0; mt < 2; mt++) {
        const int r0 = m0 + (wRow * 2 + mt) * 16 + (lane >> 2);
#pragma unroll
        for (int nt = 0; nt < 4; nt++) {
            int cc = n0 + wCol * 32 + nt * 8 + ((lane & 3) << 1);
            float b0v = __ldg(&bias[cc]), b1v = __ldg(&bias[cc + 1]);
            float* p0 = C + (size_t)r0 * SIXH + cc;
            float* p1 = p0 + (size_t)8 * SIXH;
            p0[0] = acc[mt][nt][0] + b0v;
            p0[1] = acc[mt][nt][1] + b1v;
            p1[0] = acc[mt][nt][2] + b0v;
            p1[1] = acc[mt][nt][3] + b1v;
        }
    }
}

// ---------------- persistent recurrence kernel ------------------------------
// 128 blocks x 256 threads. Block b owns 48 z-columns (6 n-frags).
// 8 warps = 2 k-groups x (2 wr x 2 wc); warp tile 32m x 24n (M=2 chunks, N=3),
// A = h in f32 fragments (split to hi/lo in registers), B = Wh split fragments.
// k-split halves combined via smem reduction, then z += acc by group 0.
struct SlotR { float4 aF[2][2], bF[3][2]; };

__device__ __forceinline__ void ldslotR(
    SlotR& S, const float4* __restrict__ H4, const float4* __restrict__ W4,
    int aChunk0, size_t bBase, int kc0, int lane)
{
#pragma unroll
    for (int mt = 0; mt < 2; mt++)
#pragma unroll
        for (int kb = 0; kb < 2; kb++)
            S.aF[mt][kb] = __ldcg(&H4[((size_t)(aChunk0 + mt) * 128 + kc0 + kb) * 32 + lane]);
#pragma unroll
    for (int nt = 0; nt < 3; nt++)
#pragma unroll
        for (int kb = 0; kb < 2; kb++)
            S.bF[nt][kb] = __ldg(&W4[(bBase + (size_t)nt * 128 + kc0 + kb) * 32 + lane]);
}
__device__ __forceinline__ void mmaslotR(const SlotR& S, float acc[2][3][4]) {
#pragma unroll
    for (int kb = 0; kb < 2; kb++)
#pragma unroll
        for (int mt = 0; mt < 2; mt++) {
            float ahi[4], alo[4];
#pragma unroll
            for (int i = 0; i < 4; i++)
                f32_split_tf32((&S.aF[mt][kb].x)[i], ahi[i], alo[i]);
#pragma unroll
            for (int nt = 0; nt < 3; nt++) {
                mma_tf32(acc[mt][nt], ahi, &S.bF[nt][kb].x);
                mma_tf32(acc[mt][nt], ahi, &S.bF[nt][kb].z);
                mma_tf32(acc[mt][nt], alo, &S.bF[nt][kb].x);
            }
        }
}

__global__ void __launch_bounds__(256) recur_persist(
    const float* __restrict__ whf,   // B split fragments [1024, 6144]
    float* __restrict__ xz,          // [T,64,6144] row-major
    float* __restrict__ out_rm,      // layer1: all_h row-major dst (or null)
    float* __restrict__ af,          // layer0: split-fragment dst for layer-1 A (or null)
    float* __restrict__ hf,          // [64,1024] h f32 fragments
    float* __restrict__ hbuf, float* __restrict__ cbuf)  // row-major [64,1024]
{
    __shared__ float sred[3072];     // 12 KB k-split reduction buffer
    __shared__ float sa[8], sb[8];

    const int tid = threadIdx.x, lane = tid & 31, warp = tid >> 5;
    const int kgrp = warp >> 2;              // 0,1: k-halves
    const int wr = (warp >> 1) & 1;          // m 32-row group
    const int wc = warp & 1;                 // n 24-col group
    const int b = blockIdx.x, n0 = b * 48, NB = gridDim.x;
    const float4* W4 = (const float4*)whf;
    const float4* H4 = (const float4*)hf;
    const size_t bBase = (size_t)((n0 >> 3) + wc * 3) * 128;
    const int aChunk0 = wr * 2;
    const int kcBase = kgrp * 64;            // this group's k8-chunk range [kcBase, kcBase+64)

    for (int t = 0; t < TT; t++) {
        float* zslice = xz + (size_t)t * MB * SIXH;

        // ---------------- phase 1: z tile += h @ Wh tile ----------------
        float acc[2][3][4];
#pragma unroll
        for (int mt = 0; mt < 2; mt++)
#pragma unroll
            for (int nt = 0; nt < 3; nt++)
#pragma unroll
                for (int i = 0; i < 4; i++) acc[mt][nt][i] = 0.0f;

        SlotR s0, s1;
        ldslotR(s0, H4, W4, aChunk0, bBase, kcBase, lane);

        for (int ic = 0; ic < 32; ic += 2) {      // 32 k16 slots per half
            ldslotR(s1, H4, W4, aChunk0, bBase, kcBase + (ic + 1) * 2, lane);
            mmaslotR(s0, acc);
            if (ic + 2 < 32) ldslotR(s0, H4, W4, aChunk0, bBase, kcBase + (ic + 2) * 2, lane);
            mmaslotR(s1, acc);
        }

        // k-split reduction: group 1 stores, group 0 adds + writes z
        if (kgrp == 1) {
#pragma unroll
            for (int mt = 0; mt < 2; mt++)
#pragma unroll
                for (int nt = 0; nt < 3; nt++) {
                    int cell = ((wr * 2 + wc) * 2 + mt) * 3 + nt;
                    float* p = &sred[cell * 128 + lane * 4];
                    p[0] = acc[mt][nt][0]; p[1] = acc[mt][nt][1];
                    p[2] = acc[mt][nt][2]; p[3] = acc[mt][nt][3];
                }
        }
        __syncthreads();
        if (kgrp == 0) {
#pragma unroll
            for (int mt = 0; mt < 2; mt++) {
                const int r0 = (wr * 2 + mt) * 16 + (lane >> 2);
#pragma unroll
                for (int nt = 0; nt < 3; nt++) {
                    int cell = ((wr * 2 + wc) * 2 + mt) * 3 + nt;
                    const float* p = &sred[cell * 128 + lane * 4];
                    int cc = n0 + wc * 24 + nt * 8 + ((lane & 3) << 1);
                    float* p0 = zslice + (size_t)r0 * SIXH + cc;
                    float* p1 = p0 + (size_t)8 * SIXH;
                    p0[0] += acc[mt][nt][0] + p[0];
                    p0[1] += acc[mt][nt][1] + p[1];
                    p1[0] += acc[mt][nt][2] + p[2];
                    p1[1] += acc[mt][nt][3] + p[3];
                }
            }
        }

        grid_barrier(NB);

        // ---------------- phase 2: gate + cummax + state update ----------------
        if (b < MB) {
            const int m = b;
            const int wid = warp;
            const float* zr = zslice + (size_t)m * SIXH;

            float4 ft4 = __ldcg((const float4*)(zr + 4096 + tid * 4));
            float4 it4 = __ldcg((const float4*)(zr + 5120 + tid * 4));

            float mft = fmaxf(fmaxf(ft4.x, ft4.y), fmaxf(ft4.z, ft4.w));
            float mit = fmaxf(fmaxf(it4.x, it4.y), fmaxf(it4.z, it4.w));
#pragma unroll
            for (int o = 16; o > 0; o >>= 1) {
                mft = fmaxf(mft, __shfl_xor_sync(0xffffffffu, mft, o));
                mit = fmaxf(mit, __shfl_xor_sync(0xffffffffu, mit, o));
            }
            if (lane == 0) { sa[wid] = mft; sb[wid] = mit; }
            __syncthreads();
            mft = sa[0]; mit = sb[0];
#pragma unroll
            for (int w = 1; w < 8; w++) { mft = fmaxf(mft, sa[w]); mit = fmaxf(mit, sb[w]); }
            __syncthreads();

            float eft[4], eit[4], pft[4], pit[4];
            eft[0] = expf(ft4.x - mft); eft[1] = expf(ft4.y - mft);
            eft[2] = expf(ft4.z - mft); eft[3] = expf(ft4.w - mft);
            eit[0] = expf(it4.x - mit); eit[1] = expf(it4.y - mit);
            eit[2] = expf(it4.z - mit); eit[3] = expf(it4.w - mit);
            pft[0] = eft[0]; pit[0] = eit[0];
#pragma unroll
            for (int i = 1; i < 4; i++) { pft[i] = pft[i - 1] + eft[i]; pit[i] = pit[i - 1] + eit[i]; }
            float Sf = pft[3], Si = pit[3];

            float xf = Sf, xi = Si;
#pragma unroll
            for (int o = 1; o < 32; o <<= 1) {
                float a = __shfl_up_sync(0xffffffffu, xf, o);
                float bb = __shfl_up_sync(0xffffffffu, xi, o);
                if (lane >= o) { xf += a; xi += bb; }
            }
            if (lane == 31) { sa[wid] = xf; sb[wid] = xi; }
            __syncthreads();
            float basef = 0.0f, basei = 0.0f, totf = 0.0f, toti = 0.0f;
#pragma unroll
            for (int w = 0; w < 8; w++) {
                float va = sa[w], vb = sb[w];
                if (w < wid) { basef += va; basei += vb; }
                totf += va; toti += vb;
            }
            __syncthreads();
            float exclf = basef + xf - Sf;
            float excli = basei + xi - Si;
            float invf = 1.0f / totf, invi = 1.0f / toti;

            float4 zi4 = __ldcg((const float4*)(zr + tid * 4));
            float4 zf4 = __ldcg((const float4*)(zr + 1024 + tid * 4));
            float4 zg4 = __ldcg((const float4*)(zr + 2048 + tid * 4));
            float4 zo4 = __ldcg((const float4*)(zr + 3072 + tid * 4));
            float4 c4  = *(const float4*)(cbuf + (size_t)m * HH + tid * 4);

            float zi[4] = {zi4.x, zi4.y, zi4.z, zi4.w};
            float zf[4] = {zf4.x, zf4.y, zf4.z, zf4.w};
            float zg[4] = {zg4.x, zg4.y, zg4.z, zg4.w};
            float zo[4] = {zo4.x, zo4.y, zo4.z, zo4.w};
            float co[4] = {c4.x, c4.y, c4.z, c4.w};
            float hv[4], cv[4];
#pragma unroll
            for (int i = 0; i < 4; i++) {
                float ftil = (exclf + pft[i]) * invf;
                float itil = 1.0f - (excli + pit[i]) * invi;
                float f_t = sigm(zf[i]);
                float i_t = sigm(zi[i]);
                float o_t = sigm(zo[i]);
                float ch  = tanhf(zg[i]);
                float om  = ftil * itil;
                float fh  = f_t * om + (ftil - om);
                float ih  = i_t * om + (itil - om);
                float cn  = fh * co[i] + ih * ch;
                cv[i] = cn;
                hv[i] = o_t * tanhf(cn);
                // write h in f32 fragment layout (for next step's phase 1)
                {
                    int j = tid * 4 + i;
                    size_t chunk = (size_t)(m >> 4) * 128 + (j >> 3);
                    size_t inner = (size_t)((m & 7) * 4 + i) * 4 + ((m >> 3) & 1) + 2 * (tid & 1);
                    hf[chunk * 128 + inner] = hv[i];
                }
                if (af) {   // layer 0: write h0all split fragments for layer-1 phase A
                    float hh, hl;
                    f32_split_tf32(hv[i], hh, hl);
                    int j = tid * 4 + i;
                    size_t fa = a_frag_idx(t * MB + m, j, HH, 0);
                    af[fa] = hh;
                    af[fa + 4] = hl;
                }
            }
            size_t off = (size_t)m * HH + tid * 4;
            *(float4*)(cbuf + off) = make_float4(cv[0], cv[1], cv[2], cv[3]);
            *(float4*)(hbuf + off) = make_float4(hv[0], hv[1], hv[2], hv[3]);
            if (out_rm)
                *(float4*)(out_rm + (size_t)t * MB * HH + off) =
                    make_float4(hv[0], hv[1], hv[2], hv[3]);
        }

        grid_barrier(NB);
    }
}

// ---------------- launch ----------------------------------------------------
extern "C" void kernel_launch(void* const* d_in, const int* in_sizes, int n_in,
                              void* d_out, int out_size) {
    const float* X  = (const float*)d_in[0];   // [256,64,512]
    const float* W0 = (const float*)d_in[1];   // [1536,6144]
    const float* b0 = (const float*)d_in[2];   // [6144]
    const float* W1 = (const float*)d_in[3];   // [2048,6144]
    const float* b1 = (const float*)d_in[4];   // [6144]
    float* out = (float*)d_out;

    float *xz, *af, *wxf, *whf, *hf, *h, *c;
    unsigned* bar;
    cudaGetSymbolAddress((void**)&xz, g_xz);
    cudaGetSymbolAddress((void**)&af, g_af);
    cudaGetSymbolAddress((void**)&wxf, g_wxf);
    cudaGetSymbolAddress((void**)&whf, g_whf);
    cudaGetSymbolAddress((void**)&hf, g_hf);
    cudaGetSymbolAddress((void**)&h, g_h);
    cudaGetSymbolAddress((void**)&c, g_c);
    cudaGetSymbolAddress((void**)&bar, g_bar);

    const size_t ALLH = (size_t)TT * MB * HH;            // 16,777,216
    const size_t HN   = (size_t)2 * MB * HH;             // 131,072
    const size_t stateBytes = (size_t)MB * HH * sizeof(float);

    dim3 bigGrid(96, 128);   // 6144/64 x 16384/128

    cudaMemsetAsync(bar, 0, 2 * sizeof(unsigned));

    // ---------------- layer 0 ----------------
    {
        size_t nA = (size_t)MTOT * DD;
        prep_a_kernel<<<(unsigned)((nA + 255) / 256), 256>>>(X, af, MTOT, DD);
        size_t nBx = (size_t)DD * SIXH;
        prep_b_kernel<<<(unsigned)((nBx + 255) / 256), 256>>>(W0, wxf, DD);
        size_t nBh = (size_t)HH * SIXH;
        prep_b_kernel<<<(unsigned)((nBh + 255) / 256), 256>>>(W0 + (size_t)DD * SIXH, whf, HH);

        gemm_fragA<<<bigGrid, 256>>>(af, wxf, b0, xz, DD);

        cudaMemsetAsync(hf, 0, stateBytes);
        cudaMemsetAsync(c, 0, stateBytes);
        recur_persist<<<128, 256>>>(whf, xz, nullptr, af, hf, h, c);

        cudaMemcpyAsync(out + ALLH, h, stateBytes, cudaMemcpyDeviceToDevice);
        cudaMemcpyAsync(out + ALLH + HN, c, stateBytes, cudaMemcpyDeviceToDevice);
    }

    // ---------------- layer 1 ----------------
    {
        size_t nBx = (size_t)HH * SIXH;
        prep_b_kernel<<<(unsigned)((nBx + 255) / 256), 256>>>(W1, wxf, HH);
        prep_b_kernel<<<(unsigned)((nBx + 255) / 256), 256>>>(W1 + (size_t)HH * SIXH, whf, HH);

        gemm_fragA<<<bigGrid, 256>>>(af, wxf, b1, xz, HH);

        cudaMemsetAsync(hf, 0, stateBytes);
        cudaMemsetAsync(c, 0, stateBytes);
        recur_persist<<<128, 256>>>(whf, xz, out, nullptr, hf, h, c);

        cudaMemcpyAsync(out + ALLH + (size_t)MB * HH, h, stateBytes, cudaMemcpyDeviceToDevice);
        cudaMemcpyAsync(out + ALLH + HN + (size_t)MB * HH, c, stateBytes, cudaMemcpyDeviceToDevice);
    }
}

// round 16
// speedup vs baseline: 2.5353x; 1.0214x over previous
#include <cuda_runtime.h>
#include <cuda_bf16.h>
#include <cstdint>

#define SIXH 6144
#define TT 256
#define MB 64
#define HH 1024
#define DD 512
#define MTOT (TT * MB)   // 16384

// ---------------- scratch (device globals; no runtime allocation) ----------
__device__ float g_xz[(size_t)TT * MB * SIXH];     // 402 MB: xz (read-only after phase A)
__device__ float g_zrec[MB * SIXH];                // 1.5 MB: per-step recurrent GEMM result
__device__ float g_af[(size_t)MTOT * HH * 2];      // 134 MB: A split-fragments (X or h0all)
__device__ float g_wxf[(size_t)HH * SIXH * 2];     // 50 MB: B split-fragments Wx
__device__ float g_whf[(size_t)HH * SIXH * 2];     // 50 MB: B split-fragments Wh
__device__ float g_hf[MB * HH];                    // h f32 fragments (split in-reg)
__device__ float g_h[MB * HH];
__device__ float g_c[MB * HH];
__device__ unsigned g_bar[2];                      // [0]=count, [1]=gen

// ---------------- helpers ---------------------------------------------------
__device__ __forceinline__ void f32_split_tf32(float x, float& hi, float& lo) {
    uint32_t u;
    asm("cvt.rna.tf32.f32 %0, %1;" : "=r"(u) : "f"(x));
    hi = __uint_as_float(u);
    float r = x - hi;
    asm("cvt.rna.tf32.f32 %0, %1;" : "=r"(u) : "f"(r));
    lo = __uint_as_float(u);
}

__device__ __forceinline__ void mma_tf32(float* d, const float* a, const float* b) {
    asm volatile(
        "mma.sync.aligned.m16n8k8.row.col.f32.tf32.tf32.f32 "
        "{%0,%1,%2,%3},{%4,%5,%6,%7},{%8,%9},{%0,%1,%2,%3};"
        : "+f"(d[0]), "+f"(d[1]), "+f"(d[2]), "+f"(d[3])
        : "r"(__float_as_uint(a[0])), "r"(__float_as_uint(a[1])),
          "r"(__float_as_uint(a[2])), "r"(__float_as_uint(a[3])),
          "r"(__float_as_uint(b[0])), "r"(__float_as_uint(b[1])));
}

__device__ __forceinline__ float sigm(float x) { return 1.0f / (1.0f + expf(-x)); }

__device__ __forceinline__ unsigned ld_acquire_gpu(unsigned* p) {
    unsigned v;
    asm volatile("ld.acquire.gpu.u32 %0, [%1];" : "=r"(v) : "l"(p) : "memory");
    return v;
}
__device__ __forceinline__ void st_release_gpu(unsigned* p, unsigned v) {
    asm volatile("st.release.gpu.u32 [%0], %1;" :: "l"(p), "r"(v) : "memory");
}

// software grid barrier (sense-reversal; acquire/release; bounded spin).
// NOTE: the __threadfence() (gpu scope) doubles as the L1D invalidation
// (CCTL.IVALL) that makes plain L1-cacheable loads of cross-block data
// (h fragments) safe in the following phase.
__device__ __forceinline__ void grid_barrier(int nblocks) {
    __syncthreads();
    if (threadIdx.x == 0) {
        unsigned gen = ld_acquire_gpu(&g_bar[1]);
        __threadfence();
        unsigned arrived = atomicAdd(&g_bar[0], 1u);
        if (arrived == (unsigned)(nblocks - 1)) {
            g_bar[0] = 0u;
            st_release_gpu(&g_bar[1], gen + 1u);
        } else {
            long long spins = 0;
            while (ld_acquire_gpu(&g_bar[1]) == gen) {
                __nanosleep(32);
                if (++spins > 200000000LL) break;
            }
        }
    }
    __syncthreads();
    __threadfence();
}

// ---------------- fragment-layout index helpers ------------------------------
__device__ __forceinline__ size_t a_frag_idx(int m, int k, int K, int plane) {
    size_t chunk = (size_t)(m >> 4) * (K >> 3) + (k >> 3);
    return chunk * 256 + (size_t)((m & 7) * 4 + (k & 3)) * 8 +
           ((m >> 3) & 1) + 2 * ((k >> 2) & 1) + 4 * plane;
}
__device__ __forceinline__ size_t b_frag_idx(int k, int n, int K, int plane) {
    size_t chunk = (size_t)(n >> 3) * (K >> 3) + (k >> 3);
    return chunk * 128 + (size_t)((n & 7) * 4 + (k & 3)) * 4 + ((k >> 2) & 1) + 2 * plane;
}

// ---------------- prep kernels ----------------------------------------------
__global__ void __launch_bounds__(256) prep_a_kernel(
    const float* __restrict__ src, float* __restrict__ dst, int M, int K) {
    size_t i = (size_t)blockIdx.x * blockDim.x + threadIdx.x;
    if (i >= (size_t)M * K) return;
    int m = (int)(i / K), k = (int)(i - (size_t)m * K);
    float hi, lo;
    f32_split_tf32(src[i], hi, lo);
    size_t base = a_frag_idx(m, k, K, 0);
    dst[base] = hi;
    dst[base + 4] = lo;
}
__global__ void __launch_bounds__(256) prep_b_kernel(
    const float* __restrict__ src, float* __restrict__ dst, int K) {
    size_t i = (size_t)blockIdx.x * blockDim.x + threadIdx.x;
    if (i >= (size_t)K * SIXH) return;
    int k = (int)(i / SIXH), n = (int)(i - (size_t)k * SIXH);
    float hi, lo;
    f32_split_tf32(src[i], hi, lo);
    size_t base = b_frag_idx(k, n, K, 0);
    dst[base] = hi;
    dst[base + 2] = lo;
}

// ---------------- phase-A GEMM: direct-LDG fragment GEMM --------------------
// block 128m x 64n, 256 threads, warps 4x2, warp tile 32m x 32n (M=2, N=4).
struct SlotP { float4 aH[2][2], aL[2][2], bF[4][2]; };

__device__ __forceinline__ void ldslotP(
    SlotP& S, const float4* __restrict__ A4, const float4* __restrict__ B4,
    size_t aBase0, size_t aBase1, size_t bBase, int Kc, int kc0, int lane)
{
#pragma unroll
    for (int kb = 0; kb < 2; kb++) {
        size_t ac0 = (aBase0 + kc0 + kb) * 64 + lane * 2;
        S.aH[0][kb] = __ldg(&A4[ac0]);
        S.aL[0][kb] = __ldg(&A4[ac0 + 1]);
        size_t ac1 = (aBase1 + kc0 + kb) * 64 + lane * 2;
        S.aH[1][kb] = __ldg(&A4[ac1]);
        S.aL[1][kb] = __ldg(&A4[ac1 + 1]);
    }
#pragma unroll
    for (int nt = 0; nt < 4; nt++)
#pragma unroll
        for (int kb = 0; kb < 2; kb++)
            S.bF[nt][kb] = __ldg(&B4[(bBase + (size_t)nt * Kc + kc0 + kb) * 32 + lane]);
}
__device__ __forceinline__ void mmaslotP(const SlotP& S, float acc[2][4][4]) {
#pragma unroll
    for (int kb = 0; kb < 2; kb++)
#pragma unroll
        for (int mt = 0; mt < 2; mt++)
#pragma unroll
            for (int nt = 0; nt < 4; nt++) {
                mma_tf32(acc[mt][nt], &S.aH[mt][kb].x, &S.bF[nt][kb].x);
                mma_tf32(acc[mt][nt], &S.aH[mt][kb].x, &S.bF[nt][kb].z);
                mma_tf32(acc[mt][nt], &S.aL[mt][kb].x, &S.bF[nt][kb].x);
            }
}

__global__ void __launch_bounds__(256) gemm_fragA(
    const float* __restrict__ Af, const float* __restrict__ Bf,
    const float* __restrict__ bias, float* __restrict__ C, int K)
{
    const int tid = threadIdx.x, lane = tid & 31, warp = tid >> 5;
    const int wRow = warp >> 1, wCol = warp & 1;
    const int m0 = blockIdx.y * 128, n0 = blockIdx.x * 64;
    const int Kc = K >> 3;
    const float4* A4 = (const float4*)Af;
    const float4* B4 = (const float4*)Bf;
    const size_t aBase0 = (size_t)((m0 >> 4) + wRow * 2) * Kc;
    const size_t aBase1 = aBase0 + Kc;
    const size_t bBase = (size_t)((n0 >> 3) + wCol * 4) * Kc;

    float acc[2][4][4];
#pragma unroll
    for (int mt = 0; mt < 2; mt++)
#pragma unroll
        for (int nt = 0; nt < 4; nt++)
#pragma unroll
            for (int i = 0; i < 4; i++) acc[mt][nt][i] = 0.0f;

    SlotP s0, s1;
    ldslotP(s0, A4, B4, aBase0, aBase1, bBase, Kc, 0, lane);

    const int nk = K >> 4;
    for (int ic = 0; ic < nk; ic += 2) {
        ldslotP(s1, A4, B4, aBase0, aBase1, bBase, Kc, (ic + 1) * 2, lane);
        mmaslotP(s0, acc);
        if (ic + 2 < nk) ldslotP(s0, A4, B4, aBase0, aBase1, bBase, Kc, (ic + 2) * 2, lane);
        mmaslotP(s1, acc);
    }

#pragma unroll
    for (int mt = 0; mt < 2; mt++) {
        const int r0 = m0 + (wRow * 2 + mt) * 16 + (lane >> 2);
#pragma unroll
        for (int nt = 0; nt < 4; nt++) {
            int cc = n0 + wCol * 32 + nt * 8 + ((lane & 3) << 1);
            float b0v = __ldg(&bias[cc]), b1v = __ldg(&bias[cc + 1]);
            float* p0 = C + (size_t)r0 * SIXH + cc;
            float* p1 = p0 + (size_t)8 * SIXH;
            p0[0] = acc[mt][nt][0] + b0v;
            p0[1] = acc[mt][nt][1] + b1v;
            p1[0] = acc[mt][nt][2] + b0v;
            p1[1] = acc[mt][nt][3] + b1v;
        }
    }
}

// ---------------- persistent recurrence kernel ------------------------------
// 128 blocks x 256 threads. Block b owns 48 zrec-columns (6 n-frags).
// 8 warps = 2 k-groups x (2 wr x 2 wc); warp tile 32m x 24n.
// Phase 1 writes PURE GEMM sums to zrec (L2-hot, reused every step);
// phase 2 computes z = xz + zrec.
struct SlotR { float4 aF[2][2], bF[3][2]; };

__device__ __forceinline__ void ldslotR(
    SlotR& S, const float4* __restrict__ H4, const float4* __restrict__ W4,
    int aChunk0, size_t bBase, int kc0, int lane)
{
#pragma unroll
    for (int mt = 0; mt < 2; mt++)
#pragma unroll
        for (int kb = 0; kb < 2; kb++)
            S.aF[mt][kb] = H4[((size_t)(aChunk0 + mt) * 128 + kc0 + kb) * 32 + lane];  // L1-cacheable; barrier threadfence invalidates
#pragma unroll
    for (int nt = 0; nt < 3; nt++)
#pragma unroll
        for (int kb = 0; kb < 2; kb++)
            S.bF[nt][kb] = __ldg(&W4[(bBase + (size_t)nt * 128 + kc0 + kb) * 32 + lane]);
}
__device__ __forceinline__ void mmaslotR(const SlotR& S, float acc[2][3][4]) {
#pragma unroll
    for (int kb = 0; kb < 2; kb++)
#pragma unroll
        for (int mt = 0; mt < 2; mt++) {
            float ahi[4], alo[4];
#pragma unroll
            for (int i = 0; i < 4; i++)
                f32_split_tf32((&S.aF[mt][kb].x)[i], ahi[i], alo[i]);
#pragma unroll
            for (int nt = 0; nt < 3; nt++) {
                mma_tf32(acc[mt][nt], ahi, &S.bF[nt][kb].x);
                mma_tf32(acc[mt][nt], ahi, &S.bF[nt][kb].z);
                mma_tf32(acc[mt][nt], alo, &S.bF[nt][kb].x);
            }
        }
}

__global__ void __launch_bounds__(256) recur_persist(
    const float* __restrict__ whf,   // B split fragments [1024, 6144]
    const float* __restrict__ xz,    // [T,64,6144] row-major (read-only)
    float* __restrict__ zrec,        // [64,6144] per-step recurrent sums
    float* __restrict__ out_rm,      // layer1: all_h row-major dst (or null)
    float* __restrict__ af,          // layer0: split-fragment dst for layer-1 A (or null)
    float* __restrict__ hf,          // [64,1024] h f32 fragments
    float* __restrict__ hbuf, float* __restrict__ cbuf)  // row-major [64,1024]
{
    __shared__ float sred[3072];     // 12 KB k-split reduction buffer
    __shared__ float sa[8], sb[8];

    const int tid = threadIdx.x, lane = tid & 31, warp = tid >> 5;
    const int kgrp = warp >> 2;              // 0,1: k-halves
    const int wr = (warp >> 1) & 1;          // m 32-row group
    const int wc = warp & 1;                 // n 24-col group
    const int b = blockIdx.x, n0 = b * 48, NB = gridDim.x;
    const float4* W4 = (const float4*)whf;
    const float4* H4 = (const float4*)hf;
    const size_t bBase = (size_t)((n0 >> 3) + wc * 3) * 128;
    const int aChunk0 = wr * 2;
    const int kcBase = kgrp * 64;

    for (int t = 0; t < TT; t++) {
        const float* xzs = xz + (size_t)t * MB * SIXH;

        // ---------------- phase 1: zrec tile = h @ Wh tile ----------------
        float acc[2][3][4];
#pragma unroll
        for (int mt = 0; mt < 2; mt++)
#pragma unroll
            for (int nt = 0; nt < 3; nt++)
#pragma unroll
                for (int i = 0; i < 4; i++) acc[mt][nt][i] = 0.0f;

        SlotR s0, s1;
        ldslotR(s0, H4, W4, aChunk0, bBase, kcBase, lane);

        for (int ic = 0; ic < 32; ic += 2) {
            ldslotR(s1, H4, W4, aChunk0, bBase, kcBase + (ic + 1) * 2, lane);
            mmaslotR(s0, acc);
            if (ic + 2 < 32) ldslotR(s0, H4, W4, aChunk0, bBase, kcBase + (ic + 2) * 2, lane);
            mmaslotR(s1, acc);
        }

        // k-split reduction: group 1 stores, group 0 adds + pure-stores zrec
        if (kgrp == 1) {
#pragma unroll
            for (int mt = 0; mt < 2; mt++)
#pragma unroll
                for (int nt = 0; nt < 3; nt++) {
                    int cell = ((wr * 2 + wc) * 2 + mt) * 3 + nt;
                    float* p = &sred[cell * 128 + lane * 4];
                    p[0] = acc[mt][nt][0]; p[1] = acc[mt][nt][1];
                    p[2] = acc[mt][nt][2]; p[3] = acc[mt][nt][3];
                }
        }
        __syncthreads();
        if (kgrp == 0) {
#pragma unroll
            for (int mt = 0; mt < 2; mt++) {
                const int r0 = (wr * 2 + mt) * 16 + (lane >> 2);
#pragma unroll
                for (int nt = 0; nt < 3; nt++) {
                    int cell = ((wr * 2 + wc) * 2 + mt) * 3 + nt;
                    const float* p = &sred[cell * 128 + lane * 4];
                    int cc = n0 + wc * 24 + nt * 8 + ((lane & 3) << 1);
                    float* p0 = zrec + (size_t)r0 * SIXH + cc;
                    float* p1 = p0 + (size_t)8 * SIXH;
                    p0[0] = acc[mt][nt][0] + p[0];
                    p0[1] = acc[mt][nt][1] + p[1];
                    p1[0] = acc[mt][nt][2] + p[2];
                    p1[1] = acc[mt][nt][3] + p[3];
                }
            }
        }

        grid_barrier(NB);

        // ---------------- phase 2: gate + cummax + state update ----------------
        if (b < MB) {
            const int m = b;
            const int wid = warp;
            const float* xr = xzs + (size_t)m * SIXH;
            const float* rr = zrec + (size_t)m * SIXH;

            float4 fx = __ldcg((const float4*)(xr + 4096 + tid * 4));
            float4 fr = __ldcg((const float4*)(rr + 4096 + tid * 4));
            float4 ix = __ldcg((const float4*)(xr + 5120 + tid * 4));
            float4 ir = __ldcg((const float4*)(rr + 5120 + tid * 4));
            float4 ft4 = make_float4(fx.x + fr.x, fx.y + fr.y, fx.z + fr.z, fx.w + fr.w);
            float4 it4 = make_float4(ix.x + ir.x, ix.y + ir.y, ix.z + ir.z, ix.w + ir.w);

            float mft = fmaxf(fmaxf(ft4.x, ft4.y), fmaxf(ft4.z, ft4.w));
            float mit = fmaxf(fmaxf(it4.x, it4.y), fmaxf(it4.z, it4.w));
#pragma unroll
            for (int o = 16; o > 0; o >>= 1) {
                mft = fmaxf(mft, __shfl_xor_sync(0xffffffffu, mft, o));
                mit = fmaxf(mit, __shfl_xor_sync(0xffffffffu, mit, o));
            }
            if (lane == 0) { sa[wid] = mft; sb[wid] = mit; }
            __syncthreads();
            mft = sa[0]; mit = sb[0];
#pragma unroll
            for (int w = 1; w < 8; w++) { mft = fmaxf(mft, sa[w]); mit = fmaxf(mit, sb[w]); }
            __syncthreads();

            float eft[4], eit[4], pft[4], pit[4];
            eft[0] = expf(ft4.x - mft); eft[1] = expf(ft4.y - mft);
            eft[2] = expf(ft4.z - mft); eft[3] = expf(ft4.w - mft);
            eit[0] = expf(it4.x - mit); eit[1] = expf(it4.y - mit);
            eit[2] = expf(it4.z - mit); eit[3] = expf(it4.w - mit);
            pft[0] = eft[0]; pit[0] = eit[0];
#pragma unroll
            for (int i = 1; i < 4; i++) { pft[i] = pft[i - 1] + eft[i]; pit[i] = pit[i - 1] + eit[i]; }
            float Sf = pft[3], Si = pit[3];

            float xf = Sf, xi = Si;
#pragma unroll
            for (int o = 1; o < 32; o <<= 1) {
                float a = __shfl_up_sync(0xffffffffu, xf, o);
                float bb = __shfl_up_sync(0xffffffffu, xi, o);
                if (lane >= o) { xf += a; xi += bb; }
            }
            if (lane == 31) { sa[wid] = xf; sb[wid] = xi; }
            __syncthreads();
            float basef = 0.0f, basei = 0.0f, totf = 0.0f, toti = 0.0f;
#pragma unroll
            for (int w = 0; w < 8; w++) {
                float va = sa[w], vb = sb[w];
                if (w < wid) { basef += va; basei += vb; }
                totf += va; toti += vb;
            }
            __syncthreads();
            float exclf = basef + xf - Sf;
            float excli = basei + xi - Si;
            float invf = 1.0f / totf, invi = 1.0f / toti;

            float4 zix = __ldcg((const float4*)(xr + tid * 4));
            float4 zir = __ldcg((const float4*)(rr + tid * 4));
            float4 zfx = __ldcg((const float4*)(xr + 1024 + tid * 4));
            float4 zfr = __ldcg((const float4*)(rr + 1024 + tid * 4));
            float4 zgx = __ldcg((const float4*)(xr + 2048 + tid * 4));
            float4 zgr = __ldcg((const float4*)(rr + 2048 + tid * 4));
            float4 zox = __ldcg((const float4*)(xr + 3072 + tid * 4));
            float4 zor = __ldcg((const float4*)(rr + 3072 + tid * 4));
            float4 c4  = *(const float4*)(cbuf + (size_t)m * HH + tid * 4);

            float zi[4] = {zix.x + zir.x, zix.y + zir.y, zix.z + zir.z, zix.w + zir.w};
            float zf[4] = {zfx.x + zfr.x, zfx.y + zfr.y, zfx.z + zfr.z, zfx.w + zfr.w};
            float zg[4] = {zgx.x + zgr.x, zgx.y + zgr.y, zgx.z + zgr.z, zgx.w + zgr.w};
            float zo[4] = {zox.x + zor.x, zox.y + zor.y, zox.z + zor.z, zox.w + zor.w};
            float co[4] = {c4.x, c4.y, c4.z, c4.w};
            float hv[4], cv[4];
#pragma unroll
            for (int i = 0; i < 4; i++) {
                float ftil = (exclf + pft[i]) * invf;
                float itil = 1.0f - (excli + pit[i]) * invi;
                float f_t = sigm(zf[i]);
                float i_t = sigm(zi[i]);
                float o_t = sigm(zo[i]);
                float ch  = tanhf(zg[i]);
                float om  = ftil * itil;
                float fh  = f_t * om + (ftil - om);
                float ih  = i_t * om + (itil - om);
                float cn  = fh * co[i] + ih * ch;
                cv[i] = cn;
                hv[i] = o_t * tanhf(cn);
                // write h in f32 fragment layout (for next step's phase 1)
                {
                    int j = tid * 4 + i;
                    size_t chunk = (size_t)(m >> 4) * 128 + (j >> 3);
                    size_t inner = (size_t)((m & 7) * 4 + i) * 4 + ((m >> 3) & 1) + 2 * (tid & 1);
                    hf[chunk * 128 + inner] = hv[i];
                }
                if (af) {   // layer 0: write h0all split fragments for layer-1 phase A
                    float hh, hl;
                    f32_split_tf32(hv[i], hh, hl);
                    int j = tid * 4 + i;
                    size_t fa = a_frag_idx(t * MB + m, j, HH, 0);
                    af[fa] = hh;
                    af[fa + 4] = hl;
                }
            }
            size_t off = (size_t)m * HH + tid * 4;
            *(float4*)(cbuf + off) = make_float4(cv[0], cv[1], cv[2], cv[3]);
            *(float4*)(hbuf + off) = make_float4(hv[0], hv[1], hv[2], hv[3]);
            if (out_rm)
                *(float4*)(out_rm + (size_t)t * MB * HH + off) =
                    make_float4(hv[0], hv[1], hv[2], hv[3]);
        }

        grid_barrier(NB);
    }
}

// ---------------- launch ----------------------------------------------------
extern "C" void kernel_launch(void* const* d_in, const int* in_sizes, int n_in,
                              void* d_out, int out_size) {
    const float* X  = (const float*)d_in[0];   // [256,64,512]
    const float* W0 = (const float*)d_in[1];   // [1536,6144]
    const float* b0 = (const float*)d_in[2];   // [6144]
    const float* W1 = (const float*)d_in[3];   // [2048,6144]
    const float* b1 = (const float*)d_in[4];   // [6144]
    float* out = (float*)d_out;

    float *xz, *zrec, *af, *wxf, *whf, *hf, *h, *c;
    unsigned* bar;
    cudaGetSymbolAddress((void**)&xz, g_xz);
    cudaGetSymbolAddress((void**)&zrec, g_zrec);
    cudaGetSymbolAddress((void**)&af, g_af);
    cudaGetSymbolAddress((void**)&wxf, g_wxf);
    cudaGetSymbolAddress((void**)&whf, g_whf);
    cudaGetSymbolAddress((void**)&hf, g_hf);
    cudaGetSymbolAddress((void**)&h, g_h);
    cudaGetSymbolAddress((void**)&c, g_c);
    cudaGetSymbolAddress((void**)&bar, g_bar);

    const size_t ALLH = (size_t)TT * MB * HH;            // 16,777,216
    const size_t HN   = (size_t)2 * MB * HH;             // 131,072
    const size_t stateBytes = (size_t)MB * HH * sizeof(float);

    dim3 bigGrid(96, 128);   // 6144/64 x 16384/128

    cudaMemsetAsync(bar, 0, 2 * sizeof(unsigned));

    // ---------------- layer 0 ----------------
    {
        size_t nA = (size_t)MTOT * DD;
        prep_a_kernel<<<(unsigned)((nA + 255) / 256), 256>>>(X, af, MTOT, DD);
        size_t nBx = (size_t)DD * SIXH;
        prep_b_kernel<<<(unsigned)((nBx + 255) / 256), 256>>>(W0, wxf, DD);
        size_t nBh = (size_t)HH * SIXH;
        prep_b_kernel<<<(unsigned)((nBh + 255) / 256), 256>>>(W0 + (size_t)DD * SIXH, whf, HH);

        gemm_fragA<<<bigGrid, 256>>>(af, wxf, b0, xz, DD);

        cudaMemsetAsync(hf, 0, stateBytes);
        cudaMemsetAsync(c, 0, stateBytes);
        recur_persist<<<128, 256>>>(whf, xz, zrec, nullptr, af, hf, h, c);

        cudaMemcpyAsync(out + ALLH, h, stateBytes, cudaMemcpyDeviceToDevice);
        cudaMemcpyAsync(out + ALLH + HN, c, stateBytes, cudaMemcpyDeviceToDevice);
    }

    // ---------------- layer 1 ----------------
    {
        size_t nBx = (size_t)HH * SIXH;
        prep_b_kernel<<<(unsigned)((nBx + 255) / 256), 256>>>(W1, wxf, HH);
        prep_b_kernel<<<(unsigned)((nBx + 255) / 256), 256>>>(W1 + (size_t)HH * SIXH, whf, HH);

        gemm_fragA<<<bigGrid, 256>>>(af, wxf, b1, xz, HH);

        cudaMemsetAsync(hf, 0, stateBytes);
        cudaMemsetAsync(c, 0, stateBytes);
        recur_persist<<<128, 256>>>(whf, xz, zrec, out, nullptr, hf, h, c);

        cudaMemcpyAsync(out + ALLH + (size_t)MB * HH, h, stateBytes, cudaMemcpyDeviceToDevice);
        cudaMemcpyAsync(out + ALLH + HN + (size_t)MB * HH, c, stateBytes, cudaMemcpyDeviceToDevice);
    }
}